// round 1
// baseline (speedup 1.0000x reference)
#include <cuda_runtime.h>
#include <math.h>

#define BATCH 1024
#define IN_DIM 768
#define HID 1024
#define CLIP_D 512
#define NG 4
#define DS 64
#define DC 4
#define HD 64
#define DIN 2048
#define NH 32
#define CONV_DIM 2560
#define DINP 4640
#define EPS 1e-5f

// ---------------- scratch (device globals; no runtime allocation) ----------
__device__ float g_x[BATCH * IN_DIM];        // post-layernorm
__device__ float g_gated[BATCH * HID];       // gated hidden
__device__ float g_zx[BATCH * DINP];         // zxbcdt
__device__ float g_y[BATCH * DIN];           // normalized ssm branch output
__device__ float g_outpre[BATCH * HID];      // ssm_out + gated
__device__ float g_out[BATCH * HID];         // after out gate

__device__ __forceinline__ float sigmoidf_(float x) { return 1.f / (1.f + expf(-x)); }

// ---------------- LayerNorm: one block per row ------------------------------
__global__ __launch_bounds__(256) void ln_kernel(const float* __restrict__ f,
                                                 const float* __restrict__ w,
                                                 const float* __restrict__ bb) {
    int b = blockIdx.x, t = threadIdx.x;
    const float* row = f + (size_t)b * IN_DIM;
    float s = 0.f, s2 = 0.f;
    for (int i = t; i < IN_DIM; i += 256) { float v = row[i]; s += v; s2 += v * v; }
#pragma unroll
    for (int o = 16; o; o >>= 1) {
        s  += __shfl_xor_sync(0xffffffffu, s, o);
        s2 += __shfl_xor_sync(0xffffffffu, s2, o);
    }
    __shared__ float rs[8], rs2[8], stats[2];
    int wid = t >> 5, lane = t & 31;
    if (lane == 0) { rs[wid] = s; rs2[wid] = s2; }
    __syncthreads();
    if (t == 0) {
        float a = 0.f, a2 = 0.f;
        for (int i = 0; i < 8; i++) { a += rs[i]; a2 += rs2[i]; }
        float mu = a / IN_DIM;
        float var = a2 / IN_DIM - mu * mu;
        stats[0] = mu;
        stats[1] = rsqrtf(var + EPS);
    }
    __syncthreads();
    float mu = stats[0], inv = stats[1];
    for (int i = t; i < IN_DIM; i += 256)
        g_x[(size_t)b * IN_DIM + i] = (row[i] - mu) * inv * w[i] + bb[i];
}

// ---------------- generic tiled fp32 GEMM: C = A[M,K] @ B[N,K]^T ------------
// MODE 0: C = acc
// MODE 1: C = acc + extra[m,n]
// MODE 2: C = extra[m,n] * sigmoid(acc + bias[n])
// MODE 3: C = acc + bias[n]
#define BM 128
#define BN 64
#define BK 16

template <int MODE>
__global__ __launch_bounds__(256) void gemm_k(const float* __restrict__ A,
                                              const float* __restrict__ B,
                                              float* __restrict__ C,
                                              int M, int N, int K,
                                              const float* __restrict__ bias,
                                              const float* __restrict__ extra) {
    __shared__ __align__(16) float As[BK][BM + 4];
    __shared__ __align__(16) float Bs[BK][BN + 4];
    int t = threadIdx.x;
    int tx = t & 15, ty = t >> 4;
    int m0 = blockIdx.y * BM, n0 = blockIdx.x * BN;

    float acc[8][4];
#pragma unroll
    for (int i = 0; i < 8; i++)
#pragma unroll
        for (int j = 0; j < 4; j++) acc[i][j] = 0.f;

    for (int k0 = 0; k0 < K; k0 += BK) {
#pragma unroll
        for (int i = 0; i < 8; i++) {
            int idx = t + i * 256;
            int r = idx >> 4, c = idx & 15;
            As[c][r] = A[(size_t)(m0 + r) * K + k0 + c];
        }
#pragma unroll
        for (int i = 0; i < 4; i++) {
            int idx = t + i * 256;
            int r = idx >> 4, c = idx & 15;
            int n = n0 + r;
            Bs[c][r] = (n < N) ? B[(size_t)n * K + k0 + c] : 0.f;
        }
        __syncthreads();
#pragma unroll
        for (int kk = 0; kk < BK; kk++) {
            float4 a0 = *(const float4*)&As[kk][ty * 8];
            float4 a1 = *(const float4*)&As[kk][ty * 8 + 4];
            float4 bv = *(const float4*)&Bs[kk][tx * 4];
            float av[8] = {a0.x, a0.y, a0.z, a0.w, a1.x, a1.y, a1.z, a1.w};
            float bw[4] = {bv.x, bv.y, bv.z, bv.w};
#pragma unroll
            for (int i = 0; i < 8; i++)
#pragma unroll
                for (int j = 0; j < 4; j++) acc[i][j] += av[i] * bw[j];
        }
        __syncthreads();
    }
#pragma unroll
    for (int i = 0; i < 8; i++) {
        int m = m0 + ty * 8 + i;
#pragma unroll
        for (int j = 0; j < 4; j++) {
            int n = n0 + tx * 4 + j;
            if (n < N) {
                float v = acc[i][j];
                if (MODE == 1) v += extra[(size_t)m * N + n];
                else if (MODE == 2) v = extra[(size_t)m * N + n] * sigmoidf_(v + bias[n]);
                else if (MODE == 3) v += bias[n];
                C[(size_t)m * N + n] = v;
            }
        }
    }
}

// ---------------- dual GEMM + sigmoid gate ----------------------------------
// gated = (x @ Wip^T + bip) * sigmoid(x @ Wig^T + big); M=BATCH, N=HID, K=IN_DIM
__global__ __launch_bounds__(256) void dualgemm_k(const float* __restrict__ B1,   // w_input_proj [HID, IN_DIM]
                                                  const float* __restrict__ bias1,
                                                  const float* __restrict__ B2,   // w_in_gate [HID, IN_DIM]
                                                  const float* __restrict__ bias2) {
    __shared__ __align__(16) float As[BK][BM + 4];
    __shared__ __align__(16) float B1s[BK][BN + 4];
    __shared__ __align__(16) float B2s[BK][BN + 4];
    int t = threadIdx.x;
    int tx = t & 15, ty = t >> 4;
    int m0 = blockIdx.y * BM, n0 = blockIdx.x * BN;

    float acc1[8][4], acc2[8][4];
#pragma unroll
    for (int i = 0; i < 8; i++)
#pragma unroll
        for (int j = 0; j < 4; j++) { acc1[i][j] = 0.f; acc2[i][j] = 0.f; }

    for (int k0 = 0; k0 < IN_DIM; k0 += BK) {
#pragma unroll
        for (int i = 0; i < 8; i++) {
            int idx = t + i * 256;
            int r = idx >> 4, c = idx & 15;
            As[c][r] = g_x[(size_t)(m0 + r) * IN_DIM + k0 + c];
        }
#pragma unroll
        for (int i = 0; i < 4; i++) {
            int idx = t + i * 256;
            int r = idx >> 4, c = idx & 15;
            B1s[c][r] = B1[(size_t)(n0 + r) * IN_DIM + k0 + c];
            B2s[c][r] = B2[(size_t)(n0 + r) * IN_DIM + k0 + c];
        }
        __syncthreads();
#pragma unroll
        for (int kk = 0; kk < BK; kk++) {
            float4 a0 = *(const float4*)&As[kk][ty * 8];
            float4 a1 = *(const float4*)&As[kk][ty * 8 + 4];
            float4 b1 = *(const float4*)&B1s[kk][tx * 4];
            float4 b2 = *(const float4*)&B2s[kk][tx * 4];
            float av[8] = {a0.x, a0.y, a0.z, a0.w, a1.x, a1.y, a1.z, a1.w};
            float b1w[4] = {b1.x, b1.y, b1.z, b1.w};
            float b2w[4] = {b2.x, b2.y, b2.z, b2.w};
#pragma unroll
            for (int i = 0; i < 8; i++)
#pragma unroll
                for (int j = 0; j < 4; j++) {
                    acc1[i][j] += av[i] * b1w[j];
                    acc2[i][j] += av[i] * b2w[j];
                }
        }
        __syncthreads();
    }
#pragma unroll
    for (int i = 0; i < 8; i++) {
        int m = m0 + ty * 8 + i;
#pragma unroll
        for (int j = 0; j < 4; j++) {
            int n = n0 + tx * 4 + j;
            float lin = acc1[i][j] + bias1[n];
            float gat = acc2[i][j] + bias2[n];
            g_gated[(size_t)m * HID + n] = lin * sigmoidf_(gat);
        }
    }
}

// ---------------- fused conv + SSM update + gated RMS norm ------------------
// one block per batch row, 256 threads
__global__ __launch_bounds__(256) void state_kernel(const float* __restrict__ conv_state,
                                                    const float* __restrict__ ssm_state,
                                                    const float* __restrict__ conv_w,
                                                    const float* __restrict__ conv_b,
                                                    const float* __restrict__ A_log,
                                                    const float* __restrict__ Dp,
                                                    const float* __restrict__ dt_bias,
                                                    const float* __restrict__ norm_w,
                                                    float* __restrict__ out_conv,
                                                    float* __restrict__ out_ssm) {
    int b = blockIdx.x, t = threadIdx.x;
    __shared__ __align__(16) float s_act[CONV_DIM];   // xs | Bs | Cs
    __shared__ float s_dt[NH], s_dA[NH], s_dp[NH];
    __shared__ __align__(16) float s_y[DIN];
    __shared__ float s_part[8][NG];
    __shared__ float s_gsum[NG];

    const float* zx = g_zx + (size_t)b * DINP;

    if (t < NH) {
        float d = zx[DIN + CONV_DIM + t] + dt_bias[t];
        float dt = (d > 20.f) ? d : log1pf(expf(d));
        s_dt[t] = dt;
        s_dA[t] = expf(-expf(A_log[t]) * dt);
        s_dp[t] = Dp[t];
    }

    // conv shift + depthwise conv + silu
    for (int c = t; c < CONV_DIM; c += 256) {
        float4 cs = *(const float4*)(conv_state + ((size_t)b * CONV_DIM + c) * 4);
        float xv = zx[DIN + c];
        float4 w4 = *(const float4*)(conv_w + (size_t)c * 4);
        float4 nc = make_float4(cs.y, cs.z, cs.w, xv);
        *(float4*)(out_conv + ((size_t)b * CONV_DIM + c) * 4) = nc;
        float s = nc.x * w4.x + nc.y * w4.y + nc.z * w4.z + nc.w * w4.w + conv_b[c];
        s_act[c] = s / (1.f + expf(-s));
    }
    __syncthreads();

    // SSM state update + y reduction: half-warp per (h,p) row
    int lane16 = t & 15;
    int half = t >> 4;  // 0..15
#pragma unroll 1
    for (int it = 0; it < DIN / 16; it++) {
        int r = it * 16 + half;
        int h = r >> 6, p = r & 63, g = h >> 3;
        size_t base = (((size_t)b * NH + h) * HD + p) * DS + lane16 * 4;
        float4 sv = *(const float4*)(ssm_state + base);
        float4 B4 = *(const float4*)&s_act[DIN + g * DS + lane16 * 4];
        float4 C4 = *(const float4*)&s_act[DIN + NG * DS + g * DS + lane16 * 4];
        float xh = s_act[h * HD + p];
        float coef = s_dt[h] * xh;
        float dA = s_dA[h];
        float4 ns;
        ns.x = sv.x * dA + coef * B4.x;
        ns.y = sv.y * dA + coef * B4.y;
        ns.z = sv.z * dA + coef * B4.z;
        ns.w = sv.w * dA + coef * B4.w;
        *(float4*)(out_ssm + base) = ns;
        float part = ns.x * C4.x + ns.y * C4.y + ns.z * C4.z + ns.w * C4.w;
#pragma unroll
        for (int o = 8; o; o >>= 1) part += __shfl_xor_sync(0xffffffffu, part, o, 16);
        if (lane16 == 0) s_y[r] = part + s_dp[h] * xh;
    }
    __syncthreads();

    // y *= silu(z); grouped RMS norm (deterministic reduction)
    float lsum[4] = {0.f, 0.f, 0.f, 0.f};
#pragma unroll
    for (int k = 0; k < 8; k++) {
        int d = t + k * 256;
        float z = zx[d];
        float yv = s_y[d] * (z / (1.f + expf(-z)));
        s_y[d] = yv;
        lsum[k >> 1] += yv * yv;
    }
    int wid = t >> 5, lane = t & 31;
#pragma unroll
    for (int gg = 0; gg < NG; gg++) {
        float v = lsum[gg];
#pragma unroll
        for (int o = 16; o; o >>= 1) v += __shfl_xor_sync(0xffffffffu, v, o);
        if (lane == 0) s_part[wid][gg] = v;
    }
    __syncthreads();
    if (t < NG) {
        float a = 0.f;
        for (int w = 0; w < 8; w++) a += s_part[w][t];
        s_gsum[t] = a;
    }
    __syncthreads();
#pragma unroll
    for (int k = 0; k < 8; k++) {
        int d = t + k * 256;
        float scale = rsqrtf(s_gsum[k >> 1] * (1.f / 512.f) + EPS);
        g_y[(size_t)b * DIN + d] = s_y[d] * scale * norm_w[d];
    }
}

// ---------------- launch ----------------------------------------------------
extern "C" void kernel_launch(void* const* d_in, const int* in_sizes, int n_in,
                              void* d_out, int out_size) {
    const float* frame_feat   = (const float*)d_in[0];
    const float* conv_state   = (const float*)d_in[1];
    const float* ssm_state    = (const float*)d_in[2];
    const float* ln_w         = (const float*)d_in[3];
    const float* ln_b         = (const float*)d_in[4];
    const float* w_in_gate    = (const float*)d_in[5];
    const float* b_in_gate    = (const float*)d_in[6];
    const float* w_input_proj = (const float*)d_in[7];
    const float* b_input_proj = (const float*)d_in[8];
    const float* w_in_proj    = (const float*)d_in[9];
    const float* conv_w       = (const float*)d_in[10];
    const float* conv_b       = (const float*)d_in[11];
    const float* A_log        = (const float*)d_in[12];
    const float* Dp           = (const float*)d_in[13];
    const float* dt_bias      = (const float*)d_in[14];
    const float* norm_w       = (const float*)d_in[15];
    const float* w_out_proj   = (const float*)d_in[16];
    const float* w_out_gate   = (const float*)d_in[17];
    const float* b_out_gate   = (const float*)d_in[18];
    const float* w_proj       = (const float*)d_in[19];
    const float* b_proj       = (const float*)d_in[20];

    float* out = (float*)d_out;
    float* out_clip = out;                                       // [1024, 512]
    float* out_conv = out + (size_t)BATCH * CLIP_D;              // [1024, 2560, 4]
    float* out_ssm = out_conv + (size_t)BATCH * CONV_DIM * DC;   // [1024, 32, 64, 64]

    float *px, *pg, *pzx, *py, *pop, *po;
    cudaGetSymbolAddress((void**)&px, g_x);
    cudaGetSymbolAddress((void**)&pg, g_gated);
    cudaGetSymbolAddress((void**)&pzx, g_zx);
    cudaGetSymbolAddress((void**)&py, g_y);
    cudaGetSymbolAddress((void**)&pop, g_outpre);
    cudaGetSymbolAddress((void**)&po, g_out);

    // 1) LayerNorm
    ln_kernel<<<BATCH, 256>>>(frame_feat, ln_w, ln_b);

    // 2) dual GEMM + sigmoid gate -> g_gated
    dualgemm_k<<<dim3(HID / BN, BATCH / BM), 256>>>(w_input_proj, b_input_proj,
                                                    w_in_gate, b_in_gate);

    // 3) zxbcdt = gated @ w_in_proj^T  [1024, 4640]
    gemm_k<0><<<dim3((DINP + BN - 1) / BN, BATCH / BM), 256>>>(
        pg, w_in_proj, pzx, BATCH, DINP, HID, nullptr, nullptr);

    // 4) conv + ssm + rmsnorm, writes new_conv / new_ssm outputs + g_y
    state_kernel<<<BATCH, 256>>>(conv_state, ssm_state, conv_w, conv_b,
                                 A_log, Dp, dt_bias, norm_w, out_conv, out_ssm);

    // 5) out_pre = y @ w_out_proj^T + gated
    gemm_k<1><<<dim3(HID / BN, BATCH / BM), 256>>>(
        py, w_out_proj, pop, BATCH, HID, DIN, nullptr, pg);

    // 6) out = out_pre * sigmoid(out_pre @ w_out_gate^T + b_out_gate)
    gemm_k<2><<<dim3(HID / BN, BATCH / BM), 256>>>(
        pop, w_out_gate, po, BATCH, HID, HID, b_out_gate, pop);

    // 7) clip = out @ w_proj^T + b_proj
    gemm_k<3><<<dim3(CLIP_D / BN, BATCH / BM), 256>>>(
        po, w_proj, out_clip, BATCH, CLIP_D, HID, b_proj, nullptr);
}

// round 3
// speedup vs baseline: 1.5557x; 1.5557x over previous
#include <cuda_runtime.h>
#include <math.h>
#include <stdint.h>

#define BATCH 1024
#define IN_DIM 768
#define HID 1024
#define CLIP_D 512
#define NG 4
#define DS 64
#define DC 4
#define HD 64
#define DIN 2048
#define NH 32
#define CONV_DIM 2560
#define DINP 4640
#define DINP_P 4736
#define EPS 1e-5f

// ---------------- scratch (device globals) ----------------------------------
__device__ float g_x_t[BATCH * IN_DIM];          // layernorm out (tf32 bits)
__device__ float g_wip_t[HID * IN_DIM];          // w_input_proj tf32
__device__ float g_wig_t[HID * IN_DIM];          // w_in_gate tf32
__device__ float g_winproj_t[DINP_P * HID];      // w_in_proj tf32, zero-padded rows
__device__ float g_woutproj_t[HID * DIN];        // w_out_proj tf32
__device__ float g_woutgate_t[HID * HID];        // w_out_gate tf32
__device__ float g_wproj_t[CLIP_D * HID];        // w_proj tf32
__device__ float g_lin[BATCH * HID];
__device__ float g_gate[BATCH * HID];
__device__ float g_gated[BATCH * HID];
__device__ float g_gated_t[BATCH * HID];
__device__ float g_zx[BATCH * DINP_P];
__device__ float g_y_t[BATCH * DIN];
__device__ float g_outpre[BATCH * HID];
__device__ float g_outpre_t[BATCH * HID];
__device__ float g_out_t[BATCH * HID];

__device__ __forceinline__ float sigmoidf_(float x) { return 1.f / (1.f + expf(-x)); }
__device__ __forceinline__ float tf32r(float x) {
    uint32_t r;
    asm("cvt.rna.tf32.f32 %0, %1;" : "=r"(r) : "f"(x));
    return __uint_as_float(r);
}

// ---------------- tf32 convert kernels --------------------------------------
__global__ __launch_bounds__(256) void cvt4_k(const float4* __restrict__ s,
                                              float4* __restrict__ d, int n4) {
    int i = blockIdx.x * 256 + threadIdx.x;
    if (i < n4) {
        float4 v = s[i];
        d[i] = make_float4(tf32r(v.x), tf32r(v.y), tf32r(v.z), tf32r(v.w));
    }
}

// pad w_in_proj [4640,1024] -> [4736,1024] tf32, pad rows = 0
__global__ __launch_bounds__(256) void cvt_pad_k(const float4* __restrict__ s,
                                                 float4* __restrict__ d) {
    int i = blockIdx.x * 256 + threadIdx.x;   // over 4736*256 float4s
    int n4 = DINP_P * (HID / 4);
    if (i < n4) {
        int row = i / (HID / 4);
        if (row < DINP) {
            float4 v = s[i];
            d[i] = make_float4(tf32r(v.x), tf32r(v.y), tf32r(v.z), tf32r(v.w));
        } else {
            d[i] = make_float4(0.f, 0.f, 0.f, 0.f);
        }
    }
}

// ---------------- LayerNorm -> tf32 ------------------------------------------
__global__ __launch_bounds__(256) void ln_kernel(const float* __restrict__ f,
                                                 const float* __restrict__ w,
                                                 const float* __restrict__ bb) {
    int b = blockIdx.x, t = threadIdx.x;
    const float* row = f + (size_t)b * IN_DIM;
    float s = 0.f, s2 = 0.f;
    for (int i = t; i < IN_DIM; i += 256) { float v = row[i]; s += v; s2 += v * v; }
#pragma unroll
    for (int o = 16; o; o >>= 1) {
        s  += __shfl_xor_sync(0xffffffffu, s, o);
        s2 += __shfl_xor_sync(0xffffffffu, s2, o);
    }
    __shared__ float rs[8], rs2[8], stats[2];
    int wid = t >> 5, lane = t & 31;
    if (lane == 0) { rs[wid] = s; rs2[wid] = s2; }
    __syncthreads();
    if (t == 0) {
        float a = 0.f, a2 = 0.f;
        for (int i = 0; i < 8; i++) { a += rs[i]; a2 += rs2[i]; }
        float mu = a / IN_DIM;
        float var = a2 / IN_DIM - mu * mu;
        stats[0] = mu;
        stats[1] = rsqrtf(var + EPS);
    }
    __syncthreads();
    float mu = stats[0], inv = stats[1];
    for (int i = t; i < IN_DIM; i += 256)
        g_x_t[(size_t)b * IN_DIM + i] = tf32r((row[i] - mu) * inv * w[i] + bb[i]);
}

// ---------------- tf32 tensor-core GEMM: C[M,N] = A[M,K] @ B[N,K]^T ----------
// block 128x128, BK=32, 3-stage cp.async, 8 warps (2 along M x 4 along N),
// warp tile 64x32, mma.m16n8k8.tf32.
// MODE 0: C = acc
// MODE 1: C = acc + extra;  Ct = tf32(C)
// MODE 2: Ct = tf32(extra * sigmoid(acc + bias))
// MODE 3: C = acc + bias
#define CP16(dst_s, src_g) \
    asm volatile("cp.async.cg.shared.global [%0], [%1], 16;" :: "r"(dst_s), "l"(src_g))

template <int MODE>
__global__ __launch_bounds__(256) void mma_gemm(const float* __restrict__ A,
                                                const float* __restrict__ Bm,
                                                float* __restrict__ C,
                                                float* __restrict__ Ct,
                                                int K, int N,
                                                const float* __restrict__ bias,
                                                const float* __restrict__ extra) {
    extern __shared__ float sm[];
    const int tid = threadIdx.x, lane = tid & 31, wid = tid >> 5;
    const int wm = wid & 1, wn = wid >> 1;          // 2 x 4 warp grid
    const int r = lane >> 2, cl = lane & 3;
    const int m0 = blockIdx.y * 128, n0 = blockIdx.x * 128;
    const int iters = K >> 5;

    float acc[4][4][4];
#pragma unroll
    for (int mi = 0; mi < 4; mi++)
#pragma unroll
        for (int ni = 0; ni < 4; ni++)
#pragma unroll
            for (int j = 0; j < 4; j++) acc[mi][ni][j] = 0.f;

    // stage layout: per stage 9216 floats (A 128x36, B 128x36)
    auto load_tile = [&](int s, int kt) {
        float* As = sm + s * 9216;
        float* Bs = As + 4608;
        int k0 = kt << 5;
#pragma unroll
        for (int it = 0; it < 4; it++) {
            int task = tid + (it << 8);
            int row = task >> 3, seg = task & 7;
            uint32_t da = (uint32_t)__cvta_generic_to_shared(As + row * 36 + (seg << 2));
            CP16(da, A + (size_t)(m0 + row) * K + k0 + (seg << 2));
            uint32_t db = (uint32_t)__cvta_generic_to_shared(Bs + row * 36 + (seg << 2));
            CP16(db, Bm + (size_t)(n0 + row) * K + k0 + (seg << 2));
        }
        asm volatile("cp.async.commit_group;");
    };

    load_tile(0, 0);
    load_tile(1, 1);

    for (int kt = 0; kt < iters; kt++) {
        asm volatile("cp.async.wait_group 1;" ::: "memory");
        __syncthreads();
        if (kt + 2 < iters) load_tile((kt + 2) % 3, kt + 2);
        else asm volatile("cp.async.commit_group;");

        const float* As = sm + (kt % 3) * 9216;
        const float* Bs = As + 4608;
#pragma unroll
        for (int kk = 0; kk < 4; kk++) {
            uint32_t af[4][4], bf[4][2];
#pragma unroll
            for (int mi = 0; mi < 4; mi++) {
                int row = wm * 64 + mi * 16 + r;
                int col = kk * 8 + cl;
                af[mi][0] = __float_as_uint(As[row * 36 + col]);
                af[mi][1] = __float_as_uint(As[(row + 8) * 36 + col]);
                af[mi][2] = __float_as_uint(As[row * 36 + col + 4]);
                af[mi][3] = __float_as_uint(As[(row + 8) * 36 + col + 4]);
            }
#pragma unroll
            for (int ni = 0; ni < 4; ni++) {
                int rb = wn * 32 + ni * 8 + r;
                int cb = kk * 8 + cl;
                bf[ni][0] = __float_as_uint(Bs[rb * 36 + cb]);
                bf[ni][1] = __float_as_uint(Bs[rb * 36 + cb + 4]);
            }
#pragma unroll
            for (int mi = 0; mi < 4; mi++)
#pragma unroll
                for (int ni = 0; ni < 4; ni++) {
                    asm volatile(
                        "mma.sync.aligned.m16n8k8.row.col.f32.tf32.tf32.f32 "
                        "{%0,%1,%2,%3}, {%4,%5,%6,%7}, {%8,%9}, {%0,%1,%2,%3};"
                        : "+f"(acc[mi][ni][0]), "+f"(acc[mi][ni][1]),
                          "+f"(acc[mi][ni][2]), "+f"(acc[mi][ni][3])
                        : "r"(af[mi][0]), "r"(af[mi][1]), "r"(af[mi][2]), "r"(af[mi][3]),
                          "r"(bf[ni][0]), "r"(bf[ni][1]));
                }
        }
        __syncthreads();
    }

    // epilogue
#pragma unroll
    for (int mi = 0; mi < 4; mi++) {
        int row0 = m0 + wm * 64 + mi * 16 + r;
#pragma unroll
        for (int ni = 0; ni < 4; ni++) {
            int col = n0 + wn * 32 + ni * 8 + 2 * cl;
#pragma unroll
            for (int half = 0; half < 2; half++) {
                int row = row0 + half * 8;
                float v0 = acc[mi][ni][half * 2];
                float v1 = acc[mi][ni][half * 2 + 1];
                size_t off = (size_t)row * N + col;
                if (MODE == 0) {
                    *(float2*)(C + off) = make_float2(v0, v1);
                } else if (MODE == 1) {
                    float2 e = *(const float2*)(extra + off);
                    v0 += e.x; v1 += e.y;
                    *(float2*)(C + off) = make_float2(v0, v1);
                    *(float2*)(Ct + off) = make_float2(tf32r(v0), tf32r(v1));
                } else if (MODE == 2) {
                    float2 e = *(const float2*)(extra + off);
                    float o0 = e.x * sigmoidf_(v0 + bias[col]);
                    float o1 = e.y * sigmoidf_(v1 + bias[col + 1]);
                    *(float2*)(Ct + off) = make_float2(tf32r(o0), tf32r(o1));
                } else {  // MODE 3
                    *(float2*)(C + off) = make_float2(v0 + bias[col], v1 + bias[col + 1]);
                }
            }
        }
    }
}

// ---------------- gate combine: gated = (lin+b1)*sigmoid(gate+b2) ------------
__global__ __launch_bounds__(256) void combine_k(const float* __restrict__ b1,
                                                 const float* __restrict__ b2) {
    int i = blockIdx.x * 256 + threadIdx.x;
    int n = i & (HID - 1);
    float v = (g_lin[i] + b1[n]) * sigmoidf_(g_gate[i] + b2[n]);
    g_gated[i] = v;
    g_gated_t[i] = tf32r(v);
}

// ---------------- fused conv + SSM update + gated RMS norm ------------------
__global__ __launch_bounds__(256) void state_kernel(const float* __restrict__ conv_state,
                                                    const float* __restrict__ ssm_state,
                                                    const float* __restrict__ conv_w,
                                                    const float* __restrict__ conv_b,
                                                    const float* __restrict__ A_log,
                                                    const float* __restrict__ Dp,
                                                    const float* __restrict__ dt_bias,
                                                    const float* __restrict__ norm_w,
                                                    float* __restrict__ out_conv,
                                                    float* __restrict__ out_ssm) {
    int b = blockIdx.x, t = threadIdx.x;
    __shared__ __align__(16) float s_act[CONV_DIM];
    __shared__ float s_dt[NH], s_dA[NH], s_dp[NH];
    __shared__ __align__(16) float s_y[DIN];
    __shared__ float s_part[8][NG];
    __shared__ float s_gsum[NG];

    const float* zx = g_zx + (size_t)b * DINP_P;

    if (t < NH) {
        float d = zx[DIN + CONV_DIM + t] + dt_bias[t];
        float dt = (d > 20.f) ? d : log1pf(expf(d));
        s_dt[t] = dt;
        s_dA[t] = expf(-expf(A_log[t]) * dt);
        s_dp[t] = Dp[t];
    }

    for (int c = t; c < CONV_DIM; c += 256) {
        float4 cs = __ldcs((const float4*)(conv_state + ((size_t)b * CONV_DIM + c) * 4));
        float xv = zx[DIN + c];
        float4 w4 = *(const float4*)(conv_w + (size_t)c * 4);
        float4 nc = make_float4(cs.y, cs.z, cs.w, xv);
        __stcs((float4*)(out_conv + ((size_t)b * CONV_DIM + c) * 4), nc);
        float s = nc.x * w4.x + nc.y * w4.y + nc.z * w4.z + nc.w * w4.w + conv_b[c];
        s_act[c] = s / (1.f + expf(-s));
    }
    __syncthreads();

    int lane16 = t & 15;
    int half = t >> 4;
#pragma unroll 1
    for (int it = 0; it < DIN / 16; it++) {
        int rr = it * 16 + half;
        int h = rr >> 6, p = rr & 63, g = h >> 3;
        size_t base = (((size_t)b * NH + h) * HD + p) * DS + lane16 * 4;
        float4 sv = __ldcs((const float4*)(ssm_state + base));
        float4 B4 = *(const float4*)&s_act[DIN + g * DS + lane16 * 4];
        float4 C4 = *(const float4*)&s_act[DIN + NG * DS + g * DS + lane16 * 4];
        float xh = s_act[h * HD + p];
        float coef = s_dt[h] * xh;
        float dA = s_dA[h];
        float4 ns;
        ns.x = sv.x * dA + coef * B4.x;
        ns.y = sv.y * dA + coef * B4.y;
        ns.z = sv.z * dA + coef * B4.z;
        ns.w = sv.w * dA + coef * B4.w;
        __stcs((float4*)(out_ssm + base), ns);
        float part = ns.x * C4.x + ns.y * C4.y + ns.z * C4.z + ns.w * C4.w;
#pragma unroll
        for (int o = 8; o; o >>= 1) part += __shfl_xor_sync(0xffffffffu, part, o, 16);
        if (lane16 == 0) s_y[rr] = part + s_dp[h] * xh;
    }
    __syncthreads();

    float lsum[4] = {0.f, 0.f, 0.f, 0.f};
#pragma unroll
    for (int k = 0; k < 8; k++) {
        int d = t + k * 256;
        float z = zx[d];
        float yv = s_y[d] * (z / (1.f + expf(-z)));
        s_y[d] = yv;
        lsum[k >> 1] += yv * yv;
    }
    int wid = t >> 5, lane = t & 31;
#pragma unroll
    for (int gg = 0; gg < NG; gg++) {
        float v = lsum[gg];
#pragma unroll
        for (int o = 16; o; o >>= 1) v += __shfl_xor_sync(0xffffffffu, v, o);
        if (lane == 0) s_part[wid][gg] = v;
    }
    __syncthreads();
    if (t < NG) {
        float a = 0.f;
        for (int w = 0; w < 8; w++) a += s_part[w][t];
        s_gsum[t] = a;
    }
    __syncthreads();
#pragma unroll
    for (int k = 0; k < 8; k++) {
        int d = t + k * 256;
        float scale = rsqrtf(s_gsum[k >> 1] * (1.f / 512.f) + EPS);
        g_y_t[(size_t)b * DIN + d] = tf32r(s_y[d] * scale * norm_w[d]);
    }
}

// ---------------- launch ----------------------------------------------------
#define GEMM_SMEM (3 * 9216 * 4)

extern "C" void kernel_launch(void* const* d_in, const int* in_sizes, int n_in,
                              void* d_out, int out_size) {
    const float* frame_feat   = (const float*)d_in[0];
    const float* conv_state   = (const float*)d_in[1];
    const float* ssm_state    = (const float*)d_in[2];
    const float* ln_w         = (const float*)d_in[3];
    const float* ln_b         = (const float*)d_in[4];
    const float* w_in_gate    = (const float*)d_in[5];
    const float* b_in_gate    = (const float*)d_in[6];
    const float* w_input_proj = (const float*)d_in[7];
    const float* b_input_proj = (const float*)d_in[8];
    const float* w_in_proj    = (const float*)d_in[9];
    const float* conv_w       = (const float*)d_in[10];
    const float* conv_b       = (const float*)d_in[11];
    const float* A_log        = (const float*)d_in[12];
    const float* Dp           = (const float*)d_in[13];
    const float* dt_bias      = (const float*)d_in[14];
    const float* norm_w       = (const float*)d_in[15];
    const float* w_out_proj   = (const float*)d_in[16];
    const float* w_out_gate   = (const float*)d_in[17];
    const float* b_out_gate   = (const float*)d_in[18];
    const float* w_proj       = (const float*)d_in[19];
    const float* b_proj       = (const float*)d_in[20];

    float* out = (float*)d_out;
    float* out_clip = out;
    float* out_conv = out + (size_t)BATCH * CLIP_D;
    float* out_ssm = out_conv + (size_t)BATCH * CONV_DIM * DC;

    float *p_xt, *p_wip, *p_wig, *p_winp, *p_wop, *p_wog, *p_wpj;
    float *p_lin, *p_gate, *p_gated, *p_gated_t, *p_zx, *p_yt, *p_op, *p_opt, *p_ot;
    cudaGetSymbolAddress((void**)&p_xt, g_x_t);
    cudaGetSymbolAddress((void**)&p_wip, g_wip_t);
    cudaGetSymbolAddress((void**)&p_wig, g_wig_t);
    cudaGetSymbolAddress((void**)&p_winp, g_winproj_t);
    cudaGetSymbolAddress((void**)&p_wop, g_woutproj_t);
    cudaGetSymbolAddress((void**)&p_wog, g_woutgate_t);
    cudaGetSymbolAddress((void**)&p_wpj, g_wproj_t);
    cudaGetSymbolAddress((void**)&p_lin, g_lin);
    cudaGetSymbolAddress((void**)&p_gate, g_gate);
    cudaGetSymbolAddress((void**)&p_gated, g_gated);
    cudaGetSymbolAddress((void**)&p_gated_t, g_gated_t);
    cudaGetSymbolAddress((void**)&p_zx, g_zx);
    cudaGetSymbolAddress((void**)&p_yt, g_y_t);
    cudaGetSymbolAddress((void**)&p_op, g_outpre);
    cudaGetSymbolAddress((void**)&p_opt, g_outpre_t);
    cudaGetSymbolAddress((void**)&p_ot, g_out_t);

    cudaFuncSetAttribute(mma_gemm<0>, cudaFuncAttributeMaxDynamicSharedMemorySize, GEMM_SMEM);
    cudaFuncSetAttribute(mma_gemm<1>, cudaFuncAttributeMaxDynamicSharedMemorySize, GEMM_SMEM);
    cudaFuncSetAttribute(mma_gemm<2>, cudaFuncAttributeMaxDynamicSharedMemorySize, GEMM_SMEM);
    cudaFuncSetAttribute(mma_gemm<3>, cudaFuncAttributeMaxDynamicSharedMemorySize, GEMM_SMEM);

    // weight conversions to tf32
    auto cvt = [&](const float* s, float* d, int n) {
        int n4 = n / 4;
        cvt4_k<<<(n4 + 255) / 256, 256>>>((const float4*)s, (float4*)d, n4);
    };
    cvt(w_input_proj, p_wip, HID * IN_DIM);
    cvt(w_in_gate, p_wig, HID * IN_DIM);
    cvt(w_out_proj, p_wop, HID * DIN);
    cvt(w_out_gate, p_wog, HID * HID);
    cvt(w_proj, p_wpj, CLIP_D * HID);
    {
        int n4 = DINP_P * (HID / 4);
        cvt_pad_k<<<(n4 + 255) / 256, 256>>>((const float4*)w_in_proj, (float4*)p_winp);
    }

    // 1) LayerNorm -> g_x_t (tf32)
    ln_kernel<<<BATCH, 256>>>(frame_feat, ln_w, ln_b);

    // 2a/2b) lin = x@Wip^T ; gate = x@Wig^T
    mma_gemm<0><<<dim3(HID / 128, BATCH / 128), 256, GEMM_SMEM>>>(
        p_xt, p_wip, p_lin, nullptr, IN_DIM, HID, nullptr, nullptr);
    mma_gemm<0><<<dim3(HID / 128, BATCH / 128), 256, GEMM_SMEM>>>(
        p_xt, p_wig, p_gate, nullptr, IN_DIM, HID, nullptr, nullptr);

    // 2c) gated = (lin+b1)*sigmoid(gate+b2)
    combine_k<<<(BATCH * HID) / 256, 256>>>(b_input_proj, b_in_gate);

    // 3) zx = gated @ w_in_proj^T  (padded N)
    mma_gemm<0><<<dim3(DINP_P / 128, BATCH / 128), 256, GEMM_SMEM>>>(
        p_gated_t, p_winp, p_zx, nullptr, HID, DINP_P, nullptr, nullptr);

    // 4) conv + ssm + rmsnorm
    state_kernel<<<BATCH, 256>>>(conv_state, ssm_state, conv_w, conv_b,
                                 A_log, Dp, dt_bias, norm_w, out_conv, out_ssm);

    // 5) outpre = y @ w_out_proj^T + gated
    mma_gemm<1><<<dim3(HID / 128, BATCH / 128), 256, GEMM_SMEM>>>(
        p_yt, p_wop, p_op, p_opt, DIN, HID, nullptr, p_gated);

    // 6) out = outpre * sigmoid(outpre @ w_out_gate^T + b)
    mma_gemm<2><<<dim3(HID / 128, BATCH / 128), 256, GEMM_SMEM>>>(
        p_opt, p_wog, nullptr, p_ot, HID, HID, b_out_gate, p_op);

    // 7) clip = out @ w_proj^T + b
    mma_gemm<3><<<dim3(CLIP_D / 128, BATCH / 128), 256, GEMM_SMEM>>>(
        p_ot, p_wpj, out_clip, nullptr, HID, CLIP_D, b_proj, nullptr);
}

// round 4
// speedup vs baseline: 1.7592x; 1.1308x over previous
#include <cuda_runtime.h>
#include <math.h>
#include <stdint.h>

#define BATCH 1024
#define IN_DIM 768
#define HID 1024
#define CLIP_D 512
#define NG 4
#define DS 64
#define DC 4
#define HD 64
#define DIN 2048
#define NH 32
#define CONV_DIM 2560
#define DINP 4640
#define DINP_P 4736
#define EPS 1e-5f

// ---------------- scratch (device globals) ----------------------------------
__device__ float g_wcat[2 * HID * IN_DIM];       // [wip ; wig] tf32  [2048,768]
__device__ float g_winproj_t[DINP_P * HID];      // w_in_proj tf32 padded
__device__ float g_woutproj_t[HID * DIN];
__device__ float g_woutgate_t[HID * HID];
__device__ float g_wproj_t[CLIP_D * HID];
__device__ float g_x_t[BATCH * IN_DIM];
__device__ float g_lg[BATCH * 2 * HID];          // [lin | gate] per row
__device__ float g_gated[BATCH * HID];
__device__ float g_gated_t[BATCH * HID];
__device__ float g_zx[BATCH * DINP_P];
__device__ float g_y_t[BATCH * DIN];
__device__ float g_outpre[BATCH * HID];
__device__ float g_outpre_t[BATCH * HID];
__device__ float g_out_t[BATCH * HID];

__device__ __forceinline__ float sigmoidf_(float x) { return 1.f / (1.f + expf(-x)); }
__device__ __forceinline__ float tf32r(float x) {
    uint32_t r;
    asm("cvt.rna.tf32.f32 %0, %1;" : "=r"(r) : "f"(x));
    return __uint_as_float(r);
}
__device__ __forceinline__ float4 tf32r4(float4 v) {
    return make_float4(tf32r(v.x), tf32r(v.y), tf32r(v.z), tf32r(v.w));
}

// ---------------- single fused weight-conversion kernel ----------------------
// regions in float4 units
#define R_WCAT  393216                 // 2048*768/4  (wip 196608 | wig 196608)
#define R_WINP  1212416                // 4736*256
#define R_WOP   524288                 // 2048*1024/4
#define R_WOG   262144
#define R_WPJ   131072
#define R_TOTAL (R_WCAT + R_WINP + R_WOP + R_WOG + R_WPJ)

__global__ __launch_bounds__(256) void cvtall_k(const float4* __restrict__ wip,
                                                const float4* __restrict__ wig,
                                                const float4* __restrict__ winp,
                                                const float4* __restrict__ wop,
                                                const float4* __restrict__ wog,
                                                const float4* __restrict__ wpj) {
    int i = blockIdx.x * 256 + threadIdx.x;
    if (i >= R_TOTAL) return;
    float4 v = make_float4(0.f, 0.f, 0.f, 0.f);
    float4* dst;
    if (i < R_WCAT) {
        dst = (float4*)g_wcat + i;
        v = (i < R_WCAT / 2) ? wip[i] : wig[i - R_WCAT / 2];
    } else if (i < R_WCAT + R_WINP) {
        int j = i - R_WCAT;
        dst = (float4*)g_winproj_t + j;
        if ((j >> 8) < DINP) v = winp[j];
    } else if (i < R_WCAT + R_WINP + R_WOP) {
        int j = i - R_WCAT - R_WINP;
        dst = (float4*)g_woutproj_t + j;
        v = wop[j];
    } else if (i < R_WCAT + R_WINP + R_WOP + R_WOG) {
        int j = i - R_WCAT - R_WINP - R_WOP;
        dst = (float4*)g_woutgate_t + j;
        v = wog[j];
    } else {
        int j = i - R_WCAT - R_WINP - R_WOP - R_WOG;
        dst = (float4*)g_wproj_t + j;
        v = wpj[j];
    }
    *dst = tf32r4(v);
}

// ---------------- LayerNorm -> tf32 ------------------------------------------
__global__ __launch_bounds__(256) void ln_kernel(const float* __restrict__ f,
                                                 const float* __restrict__ w,
                                                 const float* __restrict__ bb) {
    int b = blockIdx.x, t = threadIdx.x;
    const float* row = f + (size_t)b * IN_DIM;
    float s = 0.f, s2 = 0.f;
    for (int i = t; i < IN_DIM; i += 256) { float v = row[i]; s += v; s2 += v * v; }
#pragma unroll
    for (int o = 16; o; o >>= 1) {
        s  += __shfl_xor_sync(0xffffffffu, s, o);
        s2 += __shfl_xor_sync(0xffffffffu, s2, o);
    }
    __shared__ float rs[8], rs2[8], stats[2];
    int wid = t >> 5, lane = t & 31;
    if (lane == 0) { rs[wid] = s; rs2[wid] = s2; }
    __syncthreads();
    if (t == 0) {
        float a = 0.f, a2 = 0.f;
        for (int i = 0; i < 8; i++) { a += rs[i]; a2 += rs2[i]; }
        float mu = a / IN_DIM;
        float var = a2 / IN_DIM - mu * mu;
        stats[0] = mu;
        stats[1] = rsqrtf(var + EPS);
    }
    __syncthreads();
    float mu = stats[0], inv = stats[1];
    for (int i = t; i < IN_DIM; i += 256)
        g_x_t[(size_t)b * IN_DIM + i] = tf32r((row[i] - mu) * inv * w[i] + bb[i]);
}

// ---------------- tf32 tensor-core GEMM --------------------------------------
// C[M,N] = A[M,K] @ B[N,K]^T.  2-stage cp.async, 256 threads, BK=32.
// TILE 0: 128x64 tile, 8 warps 4x2, warp tile 32x32 (MI=2, NI=4)
// TILE 1:  64x64 tile, 8 warps 2x4, warp tile 32x16 (MI=2, NI=2)
// MODE 0: C = acc
// MODE 1: C = acc + extra; Ct = tf32(C)
// MODE 2: Ct = tf32(extra * sigmoid(acc + bias))
// MODE 3: C = acc + bias
#define CP16(dst_s, src_g) \
    asm volatile("cp.async.cg.shared.global [%0], [%1], 16;" :: "r"(dst_s), "l"(src_g))

template <int MODE, int TILE>
__global__ __launch_bounds__(256, 2) void mma_gemm(const float* __restrict__ A,
                                                   const float* __restrict__ Bm,
                                                   float* __restrict__ C,
                                                   float* __restrict__ Ct,
                                                   int K, int N,
                                                   const float* __restrict__ bias,
                                                   const float* __restrict__ extra) {
    constexpr int BM = TILE ? 64 : 128;
    constexpr int BN = 64;
    constexpr int STG = (BM + BN) * 36;      // floats per stage
    constexpr int MI = 2;
    constexpr int NI = TILE ? 2 : 4;

    extern __shared__ float sm[];
    const int tid = threadIdx.x, lane = tid & 31, wid = tid >> 5;
    const int r = lane >> 2, cl = lane & 3;
    const int MOFF = (TILE ? (wid & 1) : (wid & 3)) * 32;
    const int NOFF = TILE ? ((wid >> 1) * 16) : ((wid >> 2) * 32);
    const int m0 = blockIdx.y * BM, n0 = blockIdx.x * BN;
    const int iters = K >> 5;

    float acc[MI][NI][4];
#pragma unroll
    for (int mi = 0; mi < MI; mi++)
#pragma unroll
        for (int ni = 0; ni < NI; ni++)
#pragma unroll
            for (int j = 0; j < 4; j++) acc[mi][ni][j] = 0.f;

    auto load_tile = [&](int s, int kt) {
        float* As = sm + s * STG;
        float* Bs = As + BM * 36;
        int k0 = kt << 5;
#pragma unroll
        for (int it = 0; it < BM / 32; it++) {
            int task = tid + (it << 8);
            int row = task >> 3, seg = task & 7;
            uint32_t da = (uint32_t)__cvta_generic_to_shared(As + row * 36 + (seg << 2));
            CP16(da, A + (size_t)(m0 + row) * K + k0 + (seg << 2));
        }
#pragma unroll
        for (int it = 0; it < BN / 32; it++) {
            int task = tid + (it << 8);
            int row = task >> 3, seg = task & 7;
            uint32_t db = (uint32_t)__cvta_generic_to_shared(Bs + row * 36 + (seg << 2));
            CP16(db, Bm + (size_t)(n0 + row) * K + k0 + (seg << 2));
        }
        asm volatile("cp.async.commit_group;");
    };

    load_tile(0, 0);

    for (int kt = 0; kt < iters; kt++) {
        if (kt + 1 < iters) {
            load_tile((kt + 1) & 1, kt + 1);
            asm volatile("cp.async.wait_group 1;" ::: "memory");
        } else {
            asm volatile("cp.async.wait_group 0;" ::: "memory");
        }
        __syncthreads();

        const float* As = sm + (kt & 1) * STG;
        const float* Bs = As + BM * 36;
#pragma unroll
        for (int kk = 0; kk < 4; kk++) {
            uint32_t af[MI][4], bf[NI][2];
#pragma unroll
            for (int mi = 0; mi < MI; mi++) {
                int row = MOFF + mi * 16 + r;
                int col = kk * 8 + cl;
                af[mi][0] = __float_as_uint(As[row * 36 + col]);
                af[mi][1] = __float_as_uint(As[(row + 8) * 36 + col]);
                af[mi][2] = __float_as_uint(As[row * 36 + col + 4]);
                af[mi][3] = __float_as_uint(As[(row + 8) * 36 + col + 4]);
            }
#pragma unroll
            for (int ni = 0; ni < NI; ni++) {
                int rb = NOFF + ni * 8 + r;
                int cb = kk * 8 + cl;
                bf[ni][0] = __float_as_uint(Bs[rb * 36 + cb]);
                bf[ni][1] = __float_as_uint(Bs[rb * 36 + cb + 4]);
            }
#pragma unroll
            for (int mi = 0; mi < MI; mi++)
#pragma unroll
                for (int ni = 0; ni < NI; ni++) {
                    asm volatile(
                        "mma.sync.aligned.m16n8k8.row.col.f32.tf32.tf32.f32 "
                        "{%0,%1,%2,%3}, {%4,%5,%6,%7}, {%8,%9}, {%0,%1,%2,%3};"
                        : "+f"(acc[mi][ni][0]), "+f"(acc[mi][ni][1]),
                          "+f"(acc[mi][ni][2]), "+f"(acc[mi][ni][3])
                        : "r"(af[mi][0]), "r"(af[mi][1]), "r"(af[mi][2]), "r"(af[mi][3]),
                          "r"(bf[ni][0]), "r"(bf[ni][1]));
                }
        }
        __syncthreads();
    }

    // epilogue
#pragma unroll
    for (int mi = 0; mi < MI; mi++) {
        int row0 = m0 + MOFF + mi * 16 + r;
#pragma unroll
        for (int ni = 0; ni < NI; ni++) {
            int col = n0 + NOFF + ni * 8 + 2 * cl;
#pragma unroll
            for (int half = 0; half < 2; half++) {
                int row = row0 + half * 8;
                float v0 = acc[mi][ni][half * 2];
                float v1 = acc[mi][ni][half * 2 + 1];
                size_t off = (size_t)row * N + col;
                if (MODE == 0) {
                    *(float2*)(C + off) = make_float2(v0, v1);
                } else if (MODE == 1) {
                    float2 e = *(const float2*)(extra + off);
                    v0 += e.x; v1 += e.y;
                    *(float2*)(C + off) = make_float2(v0, v1);
                    *(float2*)(Ct + off) = make_float2(tf32r(v0), tf32r(v1));
                } else if (MODE == 2) {
                    float2 e = *(const float2*)(extra + off);
                    float o0 = e.x * sigmoidf_(v0 + bias[col]);
                    float o1 = e.y * sigmoidf_(v1 + bias[col + 1]);
                    *(float2*)(Ct + off) = make_float2(tf32r(o0), tf32r(o1));
                } else {
                    *(float2*)(C + off) = make_float2(v0 + bias[col], v1 + bias[col + 1]);
                }
            }
        }
    }
}

// ---------------- gate combine -----------------------------------------------
__global__ __launch_bounds__(256) void combine_k(const float* __restrict__ b1,
                                                 const float* __restrict__ b2) {
    int i = blockIdx.x * 256 + threadIdx.x;       // over BATCH*HID
    int b = i >> 10, n = i & (HID - 1);
    float lin = g_lg[(size_t)b * 2048 + n];
    float gat = g_lg[(size_t)b * 2048 + HID + n];
    float v = (lin + b1[n]) * sigmoidf_(gat + b2[n]);
    g_gated[i] = v;
    g_gated_t[i] = tf32r(v);
}

// ---------------- fused conv + SSM update + gated RMS norm -------------------
__global__ __launch_bounds__(256) void state_kernel(const float* __restrict__ conv_state,
                                                    const float* __restrict__ ssm_state,
                                                    const float* __restrict__ conv_w,
                                                    const float* __restrict__ conv_b,
                                                    const float* __restrict__ A_log,
                                                    const float* __restrict__ Dp,
                                                    const float* __restrict__ dt_bias,
                                                    const float* __restrict__ norm_w,
                                                    float* __restrict__ out_conv,
                                                    float* __restrict__ out_ssm) {
    int b = blockIdx.x, t = threadIdx.x;
    __shared__ __align__(16) float s_act[CONV_DIM];
    __shared__ float s_dt[NH], s_dA[NH], s_dp[NH];
    __shared__ __align__(16) float s_y[DIN];
    __shared__ float s_part[8][NG];
    __shared__ float s_gsum[NG];

    const float* zx = g_zx + (size_t)b * DINP_P;

    if (t < NH) {
        float d = zx[DIN + CONV_DIM + t] + dt_bias[t];
        float dt = (d > 20.f) ? d : log1pf(expf(d));
        s_dt[t] = dt;
        s_dA[t] = expf(-expf(A_log[t]) * dt);
        s_dp[t] = Dp[t];
    }

    for (int c = t; c < CONV_DIM; c += 256) {
        float4 cs = __ldcs((const float4*)(conv_state + ((size_t)b * CONV_DIM + c) * 4));
        float xv = zx[DIN + c];
        float4 w4 = *(const float4*)(conv_w + (size_t)c * 4);
        float4 nc = make_float4(cs.y, cs.z, cs.w, xv);
        __stcs((float4*)(out_conv + ((size_t)b * CONV_DIM + c) * 4), nc);
        float s = nc.x * w4.x + nc.y * w4.y + nc.z * w4.z + nc.w * w4.w + conv_b[c];
        s_act[c] = s / (1.f + expf(-s));
    }
    __syncthreads();

    int lane16 = t & 15;
    int half = t >> 4;
#pragma unroll 1
    for (int it = 0; it < DIN / 16; it++) {
        int rr = it * 16 + half;
        int h = rr >> 6, p = rr & 63, g = h >> 3;
        size_t base = (((size_t)b * NH + h) * HD + p) * DS + lane16 * 4;
        float4 sv = __ldcs((const float4*)(ssm_state + base));
        float4 B4 = *(const float4*)&s_act[DIN + g * DS + lane16 * 4];
        float4 C4 = *(const float4*)&s_act[DIN + NG * DS + g * DS + lane16 * 4];
        float xh = s_act[h * HD + p];
        float coef = s_dt[h] * xh;
        float dA = s_dA[h];
        float4 ns;
        ns.x = sv.x * dA + coef * B4.x;
        ns.y = sv.y * dA + coef * B4.y;
        ns.z = sv.z * dA + coef * B4.z;
        ns.w = sv.w * dA + coef * B4.w;
        __stcs((float4*)(out_ssm + base), ns);
        float part = ns.x * C4.x + ns.y * C4.y + ns.z * C4.z + ns.w * C4.w;
#pragma unroll
        for (int o = 8; o; o >>= 1) part += __shfl_xor_sync(0xffffffffu, part, o, 16);
        if (lane16 == 0) s_y[rr] = part + s_dp[h] * xh;
    }
    __syncthreads();

    float lsum[4] = {0.f, 0.f, 0.f, 0.f};
#pragma unroll
    for (int k = 0; k < 8; k++) {
        int d = t + k * 256;
        float z = zx[d];
        float yv = s_y[d] * (z / (1.f + expf(-z)));
        s_y[d] = yv;
        lsum[k >> 1] += yv * yv;
    }
    int wid = t >> 5, lane = t & 31;
#pragma unroll
    for (int gg = 0; gg < NG; gg++) {
        float v = lsum[gg];
#pragma unroll
        for (int o = 16; o; o >>= 1) v += __shfl_xor_sync(0xffffffffu, v, o);
        if (lane == 0) s_part[wid][gg] = v;
    }
    __syncthreads();
    if (t < NG) {
        float a = 0.f;
        for (int w = 0; w < 8; w++) a += s_part[w][t];
        s_gsum[t] = a;
    }
    __syncthreads();
#pragma unroll
    for (int k = 0; k < 8; k++) {
        int d = t + k * 256;
        float scale = rsqrtf(s_gsum[k >> 1] * (1.f / 512.f) + EPS);
        g_y_t[(size_t)b * DIN + d] = tf32r(s_y[d] * scale * norm_w[d]);
    }
}

// ---------------- launch ----------------------------------------------------
#define SMEM_T0 (2 * (128 + 64) * 36 * 4)   // 55296 B
#define SMEM_T1 (2 * (64 + 64) * 36 * 4)    // 36864 B

extern "C" void kernel_launch(void* const* d_in, const int* in_sizes, int n_in,
                              void* d_out, int out_size) {
    const float* frame_feat   = (const float*)d_in[0];
    const float* conv_state   = (const float*)d_in[1];
    const float* ssm_state    = (const float*)d_in[2];
    const float* ln_w         = (const float*)d_in[3];
    const float* ln_b         = (const float*)d_in[4];
    const float* w_in_gate    = (const float*)d_in[5];
    const float* b_in_gate    = (const float*)d_in[6];
    const float* w_input_proj = (const float*)d_in[7];
    const float* b_input_proj = (const float*)d_in[8];
    const float* w_in_proj    = (const float*)d_in[9];
    const float* conv_w       = (const float*)d_in[10];
    const float* conv_b       = (const float*)d_in[11];
    const float* A_log        = (const float*)d_in[12];
    const float* Dp           = (const float*)d_in[13];
    const float* dt_bias      = (const float*)d_in[14];
    const float* norm_w       = (const float*)d_in[15];
    const float* w_out_proj   = (const float*)d_in[16];
    const float* w_out_gate   = (const float*)d_in[17];
    const float* b_out_gate   = (const float*)d_in[18];
    const float* w_proj       = (const float*)d_in[19];
    const float* b_proj       = (const float*)d_in[20];

    float* out = (float*)d_out;
    float* out_clip = out;
    float* out_conv = out + (size_t)BATCH * CLIP_D;
    float* out_ssm = out_conv + (size_t)BATCH * CONV_DIM * DC;

    float *p_wcat, *p_winp, *p_wop, *p_wog, *p_wpj;
    float *p_xt, *p_lg, *p_gated, *p_gated_t, *p_zx, *p_yt, *p_op, *p_opt, *p_ot;
    cudaGetSymbolAddress((void**)&p_wcat, g_wcat);
    cudaGetSymbolAddress((void**)&p_winp, g_winproj_t);
    cudaGetSymbolAddress((void**)&p_wop, g_woutproj_t);
    cudaGetSymbolAddress((void**)&p_wog, g_woutgate_t);
    cudaGetSymbolAddress((void**)&p_wpj, g_wproj_t);
    cudaGetSymbolAddress((void**)&p_xt, g_x_t);
    cudaGetSymbolAddress((void**)&p_lg, g_lg);
    cudaGetSymbolAddress((void**)&p_gated, g_gated);
    cudaGetSymbolAddress((void**)&p_gated_t, g_gated_t);
    cudaGetSymbolAddress((void**)&p_zx, g_zx);
    cudaGetSymbolAddress((void**)&p_yt, g_y_t);
    cudaGetSymbolAddress((void**)&p_op, g_outpre);
    cudaGetSymbolAddress((void**)&p_opt, g_outpre_t);
    cudaGetSymbolAddress((void**)&p_ot, g_out_t);

    cudaFuncSetAttribute(mma_gemm<0, 0>, cudaFuncAttributeMaxDynamicSharedMemorySize, SMEM_T0);
    cudaFuncSetAttribute(mma_gemm<1, 1>, cudaFuncAttributeMaxDynamicSharedMemorySize, SMEM_T1);
    cudaFuncSetAttribute(mma_gemm<2, 1>, cudaFuncAttributeMaxDynamicSharedMemorySize, SMEM_T1);
    cudaFuncSetAttribute(mma_gemm<3, 1>, cudaFuncAttributeMaxDynamicSharedMemorySize, SMEM_T1);

    // 0) all weight conversions in one launch
    cvtall_k<<<(R_TOTAL + 255) / 256, 256>>>((const float4*)w_input_proj,
                                             (const float4*)w_in_gate,
                                             (const float4*)w_in_proj,
                                             (const float4*)w_out_proj,
                                             (const float4*)w_out_gate,
                                             (const float4*)w_proj);

    // 1) LayerNorm -> g_x_t (tf32)
    ln_kernel<<<BATCH, 256>>>(frame_feat, ln_w, ln_b);

    // 2) fused gate pair: lg = x @ [wip;wig]^T   N=2048
    mma_gemm<0, 0><<<dim3(2048 / 64, BATCH / 128), 256, SMEM_T0>>>(
        p_xt, p_wcat, p_lg, nullptr, IN_DIM, 2048, nullptr, nullptr);

    // 2c) gated = (lin+b1)*sigmoid(gate+b2)
    combine_k<<<(BATCH * HID) / 256, 256>>>(b_input_proj, b_in_gate);

    // 3) zx = gated @ w_in_proj^T (padded N)
    mma_gemm<0, 0><<<dim3(DINP_P / 64, BATCH / 128), 256, SMEM_T0>>>(
        p_gated_t, p_winp, p_zx, nullptr, HID, DINP_P, nullptr, nullptr);

    // 4) conv + ssm + rmsnorm
    state_kernel<<<BATCH, 256>>>(conv_state, ssm_state, conv_w, conv_b,
                                 A_log, Dp, dt_bias, norm_w, out_conv, out_ssm);

    // 5) outpre = y @ w_out_proj^T + gated
    mma_gemm<1, 1><<<dim3(HID / 64, BATCH / 64), 256, SMEM_T1>>>(
        p_yt, p_wop, p_op, p_opt, DIN, HID, nullptr, p_gated);

    // 6) out = outpre * sigmoid(outpre @ w_out_gate^T + b)
    mma_gemm<2, 1><<<dim3(HID / 64, BATCH / 64), 256, SMEM_T1>>>(
        p_opt, p_wog, nullptr, p_ot, HID, HID, b_out_gate, p_op);

    // 7) clip = out @ w_proj^T + b
    mma_gemm<3, 1><<<dim3(CLIP_D / 64, BATCH / 64), 256, SMEM_T1>>>(
        p_ot, p_wpj, out_clip, nullptr, HID, CLIP_D, b_proj, nullptr);
}

// round 5
// speedup vs baseline: 1.8444x; 1.0484x over previous
#include <cuda_runtime.h>
#include <math.h>
#include <stdint.h>

#define BATCH 1024
#define IN_DIM 768
#define HID 1024
#define CLIP_D 512
#define NG 4
#define DS 64
#define DC 4
#define HD 64
#define DIN 2048
#define NH 32
#define CONV_DIM 2560
#define DINP 4640
#define DINP_P 4736
#define EPS 1e-5f

// ---------------- scratch (device globals) ----------------------------------
__device__ float g_wcat[2 * HID * IN_DIM];       // row-interleaved [wip_j; wig_j] tf32
__device__ float g_winproj_t[DINP_P * HID];
__device__ float g_woutproj_t[HID * DIN];
__device__ float g_woutgate_t[HID * HID];
__device__ float g_wproj_t[CLIP_D * HID];
__device__ float g_x_t[BATCH * IN_DIM];
__device__ float g_gated[BATCH * HID];
__device__ float g_gated_t[BATCH * HID];
__device__ float g_zx[BATCH * DINP_P];
__device__ float g_y_t[BATCH * DIN];
__device__ float g_outpre[BATCH * HID];
__device__ float g_outpre_t[BATCH * HID];
__device__ float g_out_t[BATCH * HID];

__device__ __forceinline__ float sigmoidf_(float x) { return 1.f / (1.f + expf(-x)); }
__device__ __forceinline__ float tf32r(float x) {
    uint32_t r;
    asm("cvt.rna.tf32.f32 %0, %1;" : "=r"(r) : "f"(x));
    return __uint_as_float(r);
}
__device__ __forceinline__ float4 tf32r4(float4 v) {
    return make_float4(tf32r(v.x), tf32r(v.y), tf32r(v.z), tf32r(v.w));
}

// ---------------- single fused weight-conversion kernel ----------------------
#define R_WCAT  393216                 // 2048*768/4 (row-interleaved)
#define R_WINP  1212416                // 4736*256
#define R_WOP   524288
#define R_WOG   262144
#define R_WPJ   131072
#define R_TOTAL (R_WCAT + R_WINP + R_WOP + R_WOG + R_WPJ)

__global__ __launch_bounds__(256) void cvtall_k(const float4* __restrict__ wip,
                                                const float4* __restrict__ wig,
                                                const float4* __restrict__ winp,
                                                const float4* __restrict__ wop,
                                                const float4* __restrict__ wog,
                                                const float4* __restrict__ wpj) {
    int i = blockIdx.x * 256 + threadIdx.x;
    if (i >= R_TOTAL) return;
    float4 v = make_float4(0.f, 0.f, 0.f, 0.f);
    float4* dst;
    if (i < R_WCAT) {
        dst = (float4*)g_wcat + i;
        int row = i / 192, col = i - row * 192;     // 192 float4 per 768-col row
        int sr = (row >> 1) * 192 + col;
        v = (row & 1) ? wig[sr] : wip[sr];
    } else if (i < R_WCAT + R_WINP) {
        int j = i - R_WCAT;
        dst = (float4*)g_winproj_t + j;
        if ((j >> 8) < DINP) v = winp[j];
    } else if (i < R_WCAT + R_WINP + R_WOP) {
        int j = i - R_WCAT - R_WINP;
        dst = (float4*)g_woutproj_t + j;
        v = wop[j];
    } else if (i < R_WCAT + R_WINP + R_WOP + R_WOG) {
        int j = i - R_WCAT - R_WINP - R_WOP;
        dst = (float4*)g_woutgate_t + j;
        v = wog[j];
    } else {
        int j = i - R_WCAT - R_WINP - R_WOP - R_WOG;
        dst = (float4*)g_wproj_t + j;
        v = wpj[j];
    }
    *dst = tf32r4(v);
}

// ---------------- LayerNorm -> tf32 ------------------------------------------
__global__ __launch_bounds__(256) void ln_kernel(const float* __restrict__ f,
                                                 const float* __restrict__ w,
                                                 const float* __restrict__ bb) {
    int b = blockIdx.x, t = threadIdx.x;
    const float* row = f + (size_t)b * IN_DIM;
    float s = 0.f, s2 = 0.f;
    for (int i = t; i < IN_DIM; i += 256) { float v = row[i]; s += v; s2 += v * v; }
#pragma unroll
    for (int o = 16; o; o >>= 1) {
        s  += __shfl_xor_sync(0xffffffffu, s, o);
        s2 += __shfl_xor_sync(0xffffffffu, s2, o);
    }
    __shared__ float rs[8], rs2[8], stats[2];
    int wid = t >> 5, lane = t & 31;
    if (lane == 0) { rs[wid] = s; rs2[wid] = s2; }
    __syncthreads();
    if (t == 0) {
        float a = 0.f, a2 = 0.f;
        for (int i = 0; i < 8; i++) { a += rs[i]; a2 += rs2[i]; }
        float mu = a / IN_DIM;
        float var = a2 / IN_DIM - mu * mu;
        stats[0] = mu;
        stats[1] = rsqrtf(var + EPS);
    }
    __syncthreads();
    float mu = stats[0], inv = stats[1];
    for (int i = t; i < IN_DIM; i += 256)
        g_x_t[(size_t)b * IN_DIM + i] = tf32r((row[i] - mu) * inv * w[i] + bb[i]);
}

// ---------------- tf32 tensor-core GEMM --------------------------------------
// C[M,N] = A[M,K] @ B[N,K]^T.  2-stage cp.async, 256 threads, BK=32.
// Shapes: (BM,BN,MI,NI) in {(128,128,4,4), (128,64,2,4), (64,64,2,2)}
// warps_m = BM/(16*MI), warps_n = BN/(8*NI); warps_m*warps_n == 8
// MODE 0: C = acc
// MODE 1: C = acc + extra; Ct = tf32(C)
// MODE 2: Ct = tf32(extra * sigmoid(acc + bias))
// MODE 3: C = acc + bias
// MODE 4: interleaved gate pair: j=col/2; g=(v0+bias[j])*sigmoid(v1+bias2[j]);
//         C[row*HID+j]=g; Ct[row*HID+j]=tf32(g)
#define CP16(dst_s, src_g) \
    asm volatile("cp.async.cg.shared.global [%0], [%1], 16;" :: "r"(dst_s), "l"(src_g))

template <int MODE, int BM, int BN, int MI, int NI>
__global__ __launch_bounds__(256, 2) void mma_gemm(const float* __restrict__ A,
                                                   const float* __restrict__ Bm,
                                                   float* __restrict__ C,
                                                   float* __restrict__ Ct,
                                                   int K, int N,
                                                   const float* __restrict__ bias,
                                                   const float* __restrict__ bias2,
                                                   const float* __restrict__ extra) {
    constexpr int WMC = BM / (16 * MI);           // warps along M
    constexpr int STG = (BM + BN) * 36;

    extern __shared__ float sm[];
    const int tid = threadIdx.x, lane = tid & 31, wid = tid >> 5;
    const int r = lane >> 2, cl = lane & 3;
    const int MOFF = (wid % WMC) * MI * 16;
    const int NOFF = (wid / WMC) * NI * 8;
    const int m0 = blockIdx.y * BM, n0 = blockIdx.x * BN;
    const int iters = K >> 5;

    float acc[MI][NI][4];
#pragma unroll
    for (int mi = 0; mi < MI; mi++)
#pragma unroll
        for (int ni = 0; ni < NI; ni++)
#pragma unroll
            for (int j = 0; j < 4; j++) acc[mi][ni][j] = 0.f;

    auto load_tile = [&](int s, int kt) {
        float* base = sm + s * STG;
        int k0 = kt << 5;
#pragma unroll
        for (int it = 0; it < (BM + BN) / 32; it++) {
            int task = tid + (it << 8);
            int row = task >> 3, seg = (task & 7) << 2;
            const float* src = (row < BM)
                ? A + (size_t)(m0 + row) * K + k0 + seg
                : Bm + (size_t)(n0 + row - BM) * K + k0 + seg;
            uint32_t d = (uint32_t)__cvta_generic_to_shared(base + row * 36 + seg);
            CP16(d, src);
        }
        asm volatile("cp.async.commit_group;");
    };

    load_tile(0, 0);

    for (int kt = 0; kt < iters; kt++) {
        if (kt + 1 < iters) {
            load_tile((kt + 1) & 1, kt + 1);
            asm volatile("cp.async.wait_group 1;" ::: "memory");
        } else {
            asm volatile("cp.async.wait_group 0;" ::: "memory");
        }
        __syncthreads();

        const float* As = sm + (kt & 1) * STG;
        const float* Bs = As + BM * 36;
#pragma unroll
        for (int kk = 0; kk < 4; kk++) {
            uint32_t af[MI][4], bf[NI][2];
#pragma unroll
            for (int mi = 0; mi < MI; mi++) {
                int row = MOFF + mi * 16 + r;
                int col = kk * 8 + cl;
                af[mi][0] = __float_as_uint(As[row * 36 + col]);
                af[mi][1] = __float_as_uint(As[(row + 8) * 36 + col]);
                af[mi][2] = __float_as_uint(As[row * 36 + col + 4]);
                af[mi][3] = __float_as_uint(As[(row + 8) * 36 + col + 4]);
            }
#pragma unroll
            for (int ni = 0; ni < NI; ni++) {
                int rb = NOFF + ni * 8 + r;
                int cb = kk * 8 + cl;
                bf[ni][0] = __float_as_uint(Bs[rb * 36 + cb]);
                bf[ni][1] = __float_as_uint(Bs[rb * 36 + cb + 4]);
            }
#pragma unroll
            for (int mi = 0; mi < MI; mi++)
#pragma unroll
                for (int ni = 0; ni < NI; ni++) {
                    asm volatile(
                        "mma.sync.aligned.m16n8k8.row.col.f32.tf32.tf32.f32 "
                        "{%0,%1,%2,%3}, {%4,%5,%6,%7}, {%8,%9}, {%0,%1,%2,%3};"
                        : "+f"(acc[mi][ni][0]), "+f"(acc[mi][ni][1]),
                          "+f"(acc[mi][ni][2]), "+f"(acc[mi][ni][3])
                        : "r"(af[mi][0]), "r"(af[mi][1]), "r"(af[mi][2]), "r"(af[mi][3]),
                          "r"(bf[ni][0]), "r"(bf[ni][1]));
                }
        }
        __syncthreads();
    }

    // epilogue
#pragma unroll
    for (int mi = 0; mi < MI; mi++) {
        int row0 = m0 + MOFF + mi * 16 + r;
#pragma unroll
        for (int ni = 0; ni < NI; ni++) {
            int col = n0 + NOFF + ni * 8 + 2 * cl;
#pragma unroll
            for (int half = 0; half < 2; half++) {
                int row = row0 + half * 8;
                float v0 = acc[mi][ni][half * 2];
                float v1 = acc[mi][ni][half * 2 + 1];
                size_t off = (size_t)row * N + col;
                if (MODE == 0) {
                    *(float2*)(C + off) = make_float2(v0, v1);
                } else if (MODE == 1) {
                    float2 e = *(const float2*)(extra + off);
                    v0 += e.x; v1 += e.y;
                    *(float2*)(C + off) = make_float2(v0, v1);
                    *(float2*)(Ct + off) = make_float2(tf32r(v0), tf32r(v1));
                } else if (MODE == 2) {
                    float2 e = *(const float2*)(extra + off);
                    float o0 = e.x * sigmoidf_(v0 + bias[col]);
                    float o1 = e.y * sigmoidf_(v1 + bias[col + 1]);
                    *(float2*)(Ct + off) = make_float2(tf32r(o0), tf32r(o1));
                } else if (MODE == 3) {
                    *(float2*)(C + off) = make_float2(v0 + bias[col], v1 + bias[col + 1]);
                } else {  // MODE 4: interleaved gate pair
                    int j = col >> 1;
                    float g = (v0 + bias[j]) * sigmoidf_(v1 + bias2[j]);
                    size_t o = (size_t)row * HID + j;
                    C[o] = g;
                    Ct[o] = tf32r(g);
                }
            }
        }
    }
}

// ---------------- fused conv + SSM update + gated RMS norm -------------------
__global__ __launch_bounds__(256) void state_kernel(const float* __restrict__ conv_state,
                                                    const float* __restrict__ ssm_state,
                                                    const float* __restrict__ conv_w,
                                                    const float* __restrict__ conv_b,
                                                    const float* __restrict__ A_log,
                                                    const float* __restrict__ Dp,
                                                    const float* __restrict__ dt_bias,
                                                    const float* __restrict__ norm_w,
                                                    float* __restrict__ out_conv,
                                                    float* __restrict__ out_ssm) {
    int b = blockIdx.x, t = threadIdx.x;
    __shared__ __align__(16) float s_act[CONV_DIM];
    __shared__ float s_dt[NH], s_dA[NH], s_dp[NH];
    __shared__ __align__(16) float s_y[DIN];
    __shared__ float s_part[8][NG];
    __shared__ float s_gsum[NG];

    const float* zx = g_zx + (size_t)b * DINP_P;

    if (t < NH) {
        float d = zx[DIN + CONV_DIM + t] + dt_bias[t];
        float dt = (d > 20.f) ? d : log1pf(expf(d));
        s_dt[t] = dt;
        s_dA[t] = expf(-expf(A_log[t]) * dt);
        s_dp[t] = Dp[t];
    }

    for (int c = t; c < CONV_DIM; c += 256) {
        float4 cs = __ldcs((const float4*)(conv_state + ((size_t)b * CONV_DIM + c) * 4));
        float xv = zx[DIN + c];
        float4 w4 = *(const float4*)(conv_w + (size_t)c * 4);
        float4 nc = make_float4(cs.y, cs.z, cs.w, xv);
        __stcs((float4*)(out_conv + ((size_t)b * CONV_DIM + c) * 4), nc);
        float s = nc.x * w4.x + nc.y * w4.y + nc.z * w4.z + nc.w * w4.w + conv_b[c];
        s_act[c] = s / (1.f + expf(-s));
    }
    __syncthreads();

    int lane16 = t & 15;
    int half = t >> 4;
#pragma unroll 1
    for (int it = 0; it < DIN / 16; it++) {
        int rr = it * 16 + half;
        int h = rr >> 6, p = rr & 63, g = h >> 3;
        size_t base = (((size_t)b * NH + h) * HD + p) * DS + lane16 * 4;
        float4 sv = __ldcs((const float4*)(ssm_state + base));
        float4 B4 = *(const float4*)&s_act[DIN + g * DS + lane16 * 4];
        float4 C4 = *(const float4*)&s_act[DIN + NG * DS + g * DS + lane16 * 4];
        float xh = s_act[h * HD + p];
        float coef = s_dt[h] * xh;
        float dA = s_dA[h];
        float4 ns;
        ns.x = sv.x * dA + coef * B4.x;
        ns.y = sv.y * dA + coef * B4.y;
        ns.z = sv.z * dA + coef * B4.z;
        ns.w = sv.w * dA + coef * B4.w;
        __stcs((float4*)(out_ssm + base), ns);
        float part = ns.x * C4.x + ns.y * C4.y + ns.z * C4.z + ns.w * C4.w;
#pragma unroll
        for (int o = 8; o; o >>= 1) part += __shfl_xor_sync(0xffffffffu, part, o, 16);
        if (lane16 == 0) s_y[rr] = part + s_dp[h] * xh;
    }
    __syncthreads();

    float lsum[4] = {0.f, 0.f, 0.f, 0.f};
#pragma unroll
    for (int k = 0; k < 8; k++) {
        int d = t + k * 256;
        float z = zx[d];
        float yv = s_y[d] * (z / (1.f + expf(-z)));
        s_y[d] = yv;
        lsum[k >> 1] += yv * yv;
    }
    int wid = t >> 5, lane = t & 31;
#pragma unroll
    for (int gg = 0; gg < NG; gg++) {
        float v = lsum[gg];
#pragma unroll
        for (int o = 16; o; o >>= 1) v += __shfl_xor_sync(0xffffffffu, v, o);
        if (lane == 0) s_part[wid][gg] = v;
    }
    __syncthreads();
    if (t < NG) {
        float a = 0.f;
        for (int w = 0; w < 8; w++) a += s_part[w][t];
        s_gsum[t] = a;
    }
    __syncthreads();
#pragma unroll
    for (int k = 0; k < 8; k++) {
        int d = t + k * 256;
        float scale = rsqrtf(s_gsum[k >> 1] * (1.f / 512.f) + EPS);
        g_y_t[(size_t)b * DIN + d] = tf32r(s_y[d] * scale * norm_w[d]);
    }
}

// ---------------- launch ----------------------------------------------------
#define SMEM_BIG  (2 * (128 + 128) * 36 * 4)   // 73728
#define SMEM_MED  (2 * (128 + 64) * 36 * 4)    // 55296
#define SMEM_SML  (2 * (64 + 64) * 36 * 4)     // 36864

extern "C" void kernel_launch(void* const* d_in, const int* in_sizes, int n_in,
                              void* d_out, int out_size) {
    const float* frame_feat   = (const float*)d_in[0];
    const float* conv_state   = (const float*)d_in[1];
    const float* ssm_state    = (const float*)d_in[2];
    const float* ln_w         = (const float*)d_in[3];
    const float* ln_b         = (const float*)d_in[4];
    const float* w_in_gate    = (const float*)d_in[5];
    const float* b_in_gate    = (const float*)d_in[6];
    const float* w_input_proj = (const float*)d_in[7];
    const float* b_input_proj = (const float*)d_in[8];
    const float* w_in_proj    = (const float*)d_in[9];
    const float* conv_w       = (const float*)d_in[10];
    const float* conv_b       = (const float*)d_in[11];
    const float* A_log        = (const float*)d_in[12];
    const float* Dp           = (const float*)d_in[13];
    const float* dt_bias      = (const float*)d_in[14];
    const float* norm_w       = (const float*)d_in[15];
    const float* w_out_proj   = (const float*)d_in[16];
    const float* w_out_gate   = (const float*)d_in[17];
    const float* b_out_gate   = (const float*)d_in[18];
    const float* w_proj       = (const float*)d_in[19];
    const float* b_proj       = (const float*)d_in[20];

    float* out = (float*)d_out;
    float* out_clip = out;
    float* out_conv = out + (size_t)BATCH * CLIP_D;
    float* out_ssm = out_conv + (size_t)BATCH * CONV_DIM * DC;

    float *p_wcat, *p_winp, *p_wop, *p_wog, *p_wpj;
    float *p_xt, *p_gated, *p_gated_t, *p_zx, *p_yt, *p_op, *p_opt, *p_ot;
    cudaGetSymbolAddress((void**)&p_wcat, g_wcat);
    cudaGetSymbolAddress((void**)&p_winp, g_winproj_t);
    cudaGetSymbolAddress((void**)&p_wop, g_woutproj_t);
    cudaGetSymbolAddress((void**)&p_wog, g_woutgate_t);
    cudaGetSymbolAddress((void**)&p_wpj, g_wproj_t);
    cudaGetSymbolAddress((void**)&p_xt, g_x_t);
    cudaGetSymbolAddress((void**)&p_gated, g_gated);
    cudaGetSymbolAddress((void**)&p_gated_t, g_gated_t);
    cudaGetSymbolAddress((void**)&p_zx, g_zx);
    cudaGetSymbolAddress((void**)&p_yt, g_y_t);
    cudaGetSymbolAddress((void**)&p_op, g_outpre);
    cudaGetSymbolAddress((void**)&p_opt, g_outpre_t);
    cudaGetSymbolAddress((void**)&p_ot, g_out_t);

    cudaFuncSetAttribute((mma_gemm<4, 128, 64, 2, 4>), cudaFuncAttributeMaxDynamicSharedMemorySize, SMEM_MED);
    cudaFuncSetAttribute((mma_gemm<0, 128, 128, 4, 4>), cudaFuncAttributeMaxDynamicSharedMemorySize, SMEM_BIG);
    cudaFuncSetAttribute((mma_gemm<1, 128, 64, 2, 4>), cudaFuncAttributeMaxDynamicSharedMemorySize, SMEM_MED);
    cudaFuncSetAttribute((mma_gemm<2, 128, 64, 2, 4>), cudaFuncAttributeMaxDynamicSharedMemorySize, SMEM_MED);
    cudaFuncSetAttribute((mma_gemm<3, 64, 64, 2, 2>), cudaFuncAttributeMaxDynamicSharedMemorySize, SMEM_SML);

    // 0) weight conversions (one launch)
    cvtall_k<<<(R_TOTAL + 255) / 256, 256>>>((const float4*)w_input_proj,
                                             (const float4*)w_in_gate,
                                             (const float4*)w_in_proj,
                                             (const float4*)w_out_proj,
                                             (const float4*)w_out_gate,
                                             (const float4*)w_proj);

    // 1) LayerNorm -> g_x_t (tf32)
    ln_kernel<<<BATCH, 256>>>(frame_feat, ln_w, ln_b);

    // 2) gate pair GEMM, interleaved epilogue -> g_gated / g_gated_t
    mma_gemm<4, 128, 64, 2, 4><<<dim3(2048 / 64, BATCH / 128), 256, SMEM_MED>>>(
        p_xt, p_wcat, p_gated, p_gated_t, IN_DIM, 2048, b_input_proj, b_in_gate, nullptr);

    // 3) zx = gated @ w_in_proj^T (padded N) — big tile
    mma_gemm<0, 128, 128, 4, 4><<<dim3(DINP_P / 128, BATCH / 128), 256, SMEM_BIG>>>(
        p_gated_t, p_winp, p_zx, nullptr, HID, DINP_P, nullptr, nullptr, nullptr);

    // 4) conv + ssm + rmsnorm
    state_kernel<<<BATCH, 256>>>(conv_state, ssm_state, conv_w, conv_b,
                                 A_log, Dp, dt_bias, norm_w, out_conv, out_ssm);

    // 5) outpre = y @ w_out_proj^T + gated
    mma_gemm<1, 128, 64, 2, 4><<<dim3(HID / 64, BATCH / 128), 256, SMEM_MED>>>(
        p_yt, p_wop, p_op, p_opt, DIN, HID, nullptr, nullptr, p_gated);

    // 6) out = outpre * sigmoid(outpre @ w_out_gate^T + b)
    mma_gemm<2, 128, 64, 2, 4><<<dim3(HID / 64, BATCH / 128), 256, SMEM_MED>>>(
        p_opt, p_wog, nullptr, p_ot, HID, HID, b_out_gate, nullptr, p_op);

    // 7) clip = out @ w_proj^T + b
    mma_gemm<3, 64, 64, 2, 2><<<dim3(CLIP_D / 64, BATCH / 64), 256, SMEM_SML>>>(
        p_ot, p_wpj, out_clip, nullptr, HID, CLIP_D, b_proj, nullptr, nullptr);
}

// round 6
// speedup vs baseline: 1.8892x; 1.0243x over previous
#include <cuda_runtime.h>
#include <math.h>
#include <stdint.h>

#define BATCH 1024
#define IN_DIM 768
#define HID 1024
#define CLIP_D 512
#define NG 4
#define DS 64
#define DC 4
#define HD 64
#define DIN 2048
#define NH 32
#define CONV_DIM 2560
#define DINP 4640
#define DINP_P 4736
#define EPS 1e-5f

// ---------------- scratch (device globals) ----------------------------------
__device__ float g_wcat[2 * HID * IN_DIM];       // row-interleaved [wip_j; wig_j] tf32
__device__ float g_winproj_t[DINP_P * HID];
__device__ float g_woutproj_t[HID * DIN];
__device__ float g_woutgate_t[HID * HID];
__device__ float g_wproj_t[CLIP_D * HID];
__device__ float g_x_t[BATCH * IN_DIM];
__device__ float g_gated[BATCH * HID];
__device__ float g_gated_t[BATCH * HID];
__device__ float g_zx[BATCH * DINP_P];
__device__ float g_y_t[BATCH * DIN];
__device__ float g_outpre[BATCH * HID];
__device__ float g_outpre_t[BATCH * HID];
__device__ float g_out_t[BATCH * HID];

__device__ __forceinline__ float sigmoidf_(float x) { return 1.f / (1.f + expf(-x)); }
__device__ __forceinline__ float tf32r(float x) {
    uint32_t r;
    asm("cvt.rna.tf32.f32 %0, %1;" : "=r"(r) : "f"(x));
    return __uint_as_float(r);
}
__device__ __forceinline__ float4 tf32r4(float4 v) {
    return make_float4(tf32r(v.x), tf32r(v.y), tf32r(v.z), tf32r(v.w));
}

// ---------------- single fused weight-conversion kernel ----------------------
#define R_WCAT  393216                 // 2048*768/4 (row-interleaved)
#define R_WINP  1212416                // 4736*256
#define R_WOP   524288
#define R_WOG   262144
#define R_WPJ   131072
#define R_TOTAL (R_WCAT + R_WINP + R_WOP + R_WOG + R_WPJ)

__global__ __launch_bounds__(256) void cvtall_k(const float4* __restrict__ wip,
                                                const float4* __restrict__ wig,
                                                const float4* __restrict__ winp,
                                                const float4* __restrict__ wop,
                                                const float4* __restrict__ wog,
                                                const float4* __restrict__ wpj) {
    int i = blockIdx.x * 256 + threadIdx.x;
    if (i >= R_TOTAL) return;
    float4 v = make_float4(0.f, 0.f, 0.f, 0.f);
    float4* dst;
    if (i < R_WCAT) {
        dst = (float4*)g_wcat + i;
        int row = i / 192, col = i - row * 192;
        int sr = (row >> 1) * 192 + col;
        v = (row & 1) ? wig[sr] : wip[sr];
    } else if (i < R_WCAT + R_WINP) {
        int j = i - R_WCAT;
        dst = (float4*)g_winproj_t + j;
        if ((j >> 8) < DINP) v = winp[j];
    } else if (i < R_WCAT + R_WINP + R_WOP) {
        int j = i - R_WCAT - R_WINP;
        dst = (float4*)g_woutproj_t + j;
        v = wop[j];
    } else if (i < R_WCAT + R_WINP + R_WOP + R_WOG) {
        int j = i - R_WCAT - R_WINP - R_WOP;
        dst = (float4*)g_woutgate_t + j;
        v = wog[j];
    } else {
        int j = i - R_WCAT - R_WINP - R_WOP - R_WOG;
        dst = (float4*)g_wproj_t + j;
        v = wpj[j];
    }
    *dst = tf32r4(v);
}

// ---------------- LayerNorm -> tf32 ------------------------------------------
__global__ __launch_bounds__(256) void ln_kernel(const float* __restrict__ f,
                                                 const float* __restrict__ w,
                                                 const float* __restrict__ bb) {
    int b = blockIdx.x, t = threadIdx.x;
    const float* row = f + (size_t)b * IN_DIM;
    float s = 0.f, s2 = 0.f;
    for (int i = t; i < IN_DIM; i += 256) { float v = row[i]; s += v; s2 += v * v; }
#pragma unroll
    for (int o = 16; o; o >>= 1) {
        s  += __shfl_xor_sync(0xffffffffu, s, o);
        s2 += __shfl_xor_sync(0xffffffffu, s2, o);
    }
    __shared__ float rs[8], rs2[8], stats[2];
    int wid = t >> 5, lane = t & 31;
    if (lane == 0) { rs[wid] = s; rs2[wid] = s2; }
    __syncthreads();
    if (t == 0) {
        float a = 0.f, a2 = 0.f;
        for (int i = 0; i < 8; i++) { a += rs[i]; a2 += rs2[i]; }
        float mu = a / IN_DIM;
        float var = a2 / IN_DIM - mu * mu;
        stats[0] = mu;
        stats[1] = rsqrtf(var + EPS);
    }
    __syncthreads();
    float mu = stats[0], inv = stats[1];
    for (int i = t; i < IN_DIM; i += 256)
        g_x_t[(size_t)b * IN_DIM + i] = tf32r((row[i] - mu) * inv * w[i] + bb[i]);
}

// ---------------- tf32 tensor-core GEMM with ldmatrix ------------------------
// C[M,N] = A[M,K] @ B[N,K]^T.  2-stage cp.async, 256 threads, BK=32.
// Fragments loaded via ldmatrix.m8n8.b16 (tf32-as-2xb16 trick):
//   A m16k8 fragment = x4 (4 8x8-b16 matrices), B n8k8 fragment = x2.
#define CP16(dst_s, src_g) \
    asm volatile("cp.async.cg.shared.global [%0], [%1], 16;" :: "r"(dst_s), "l"(src_g))

__device__ __forceinline__ void ldsm_x4(uint32_t* f, uint32_t a) {
    asm volatile("ldmatrix.sync.aligned.m8n8.x4.shared.b16 {%0,%1,%2,%3}, [%4];"
                 : "=r"(f[0]), "=r"(f[1]), "=r"(f[2]), "=r"(f[3]) : "r"(a));
}
__device__ __forceinline__ void ldsm_x2(uint32_t* f, uint32_t a) {
    asm volatile("ldmatrix.sync.aligned.m8n8.x2.shared.b16 {%0,%1}, [%2];"
                 : "=r"(f[0]), "=r"(f[1]) : "r"(a));
}

template <int MODE, int BM, int BN, int MI, int NI>
__global__ __launch_bounds__(256, 2) void mma_gemm(const float* __restrict__ A,
                                                   const float* __restrict__ Bm,
                                                   float* __restrict__ C,
                                                   float* __restrict__ Ct,
                                                   int K, int N,
                                                   const float* __restrict__ bias,
                                                   const float* __restrict__ bias2,
                                                   const float* __restrict__ extra) {
    constexpr int WMC = BM / (16 * MI);           // warps along M
    constexpr int STG = (BM + BN) * 36;           // floats per stage

    extern __shared__ float sm[];
    const int tid = threadIdx.x, lane = tid & 31, wid = tid >> 5;
    const int r = lane >> 2, cl = lane & 3;
    const int MOFF = (wid % WMC) * MI * 16;
    const int NOFF = (wid / WMC) * NI * 8;
    const int m0 = blockIdx.y * BM, n0 = blockIdx.x * BN;
    const int iters = K >> 5;

    float acc[MI][NI][4];
#pragma unroll
    for (int mi = 0; mi < MI; mi++)
#pragma unroll
        for (int ni = 0; ni < NI; ni++)
#pragma unroll
            for (int j = 0; j < 4; j++) acc[mi][ni][j] = 0.f;

    // per-lane ldmatrix byte offsets relative to stage base
    const uint32_t sbase = (uint32_t)__cvta_generic_to_shared(sm);
    uint32_t a_off[MI], b_off[NI];
    {
        int am = lane >> 3, ai = lane & 7;
#pragma unroll
        for (int mi = 0; mi < MI; mi++)
            a_off[mi] = ((MOFF + mi * 16 + (am & 1) * 8 + ai) * 36 + (am >> 1) * 4) * 4;
        int bmm = (lane >> 3) & 1, bi = lane & 7;
#pragma unroll
        for (int ni = 0; ni < NI; ni++)
            b_off[ni] = ((BM + NOFF + ni * 8 + bi) * 36 + bmm * 4) * 4;
    }

    auto load_tile = [&](int s, int kt) {
        float* base = sm + s * STG;
        int k0 = kt << 5;
#pragma unroll
        for (int it = 0; it < (BM + BN) / 32; it++) {
            int task = tid + (it << 8);
            int row = task >> 3, seg = (task & 7) << 2;
            const float* src = (row < BM)
                ? A + (size_t)(m0 + row) * K + k0 + seg
                : Bm + (size_t)(n0 + row - BM) * K + k0 + seg;
            uint32_t d = (uint32_t)__cvta_generic_to_shared(base + row * 36 + seg);
            CP16(d, src);
        }
        asm volatile("cp.async.commit_group;");
    };

    load_tile(0, 0);

    for (int kt = 0; kt < iters; kt++) {
        if (kt + 1 < iters) {
            load_tile((kt + 1) & 1, kt + 1);
            asm volatile("cp.async.wait_group 1;" ::: "memory");
        } else {
            asm volatile("cp.async.wait_group 0;" ::: "memory");
        }
        __syncthreads();

        const uint32_t stage = sbase + (uint32_t)((kt & 1) * STG * 4);
#pragma unroll
        for (int kk = 0; kk < 4; kk++) {
            uint32_t af[MI][4], bf[NI][2];
#pragma unroll
            for (int mi = 0; mi < MI; mi++)
                ldsm_x4(af[mi], stage + a_off[mi] + kk * 32);
#pragma unroll
            for (int ni = 0; ni < NI; ni++)
                ldsm_x2(bf[ni], stage + b_off[ni] + kk * 32);
#pragma unroll
            for (int mi = 0; mi < MI; mi++)
#pragma unroll
                for (int ni = 0; ni < NI; ni++) {
                    asm volatile(
                        "mma.sync.aligned.m16n8k8.row.col.f32.tf32.tf32.f32 "
                        "{%0,%1,%2,%3}, {%4,%5,%6,%7}, {%8,%9}, {%0,%1,%2,%3};"
                        : "+f"(acc[mi][ni][0]), "+f"(acc[mi][ni][1]),
                          "+f"(acc[mi][ni][2]), "+f"(acc[mi][ni][3])
                        : "r"(af[mi][0]), "r"(af[mi][1]), "r"(af[mi][2]), "r"(af[mi][3]),
                          "r"(bf[ni][0]), "r"(bf[ni][1]));
                }
        }
        __syncthreads();
    }

    // epilogue
#pragma unroll
    for (int mi = 0; mi < MI; mi++) {
        int row0 = m0 + MOFF + mi * 16 + r;
#pragma unroll
        for (int ni = 0; ni < NI; ni++) {
            int col = n0 + NOFF + ni * 8 + 2 * cl;
#pragma unroll
            for (int half = 0; half < 2; half++) {
                int row = row0 + half * 8;
                float v0 = acc[mi][ni][half * 2];
                float v1 = acc[mi][ni][half * 2 + 1];
                size_t off = (size_t)row * N + col;
                if (MODE == 0) {
                    *(float2*)(C + off) = make_float2(v0, v1);
                } else if (MODE == 1) {
                    float2 e = *(const float2*)(extra + off);
                    v0 += e.x; v1 += e.y;
                    *(float2*)(C + off) = make_float2(v0, v1);
                    *(float2*)(Ct + off) = make_float2(tf32r(v0), tf32r(v1));
                } else if (MODE == 2) {
                    float2 e = *(const float2*)(extra + off);
                    float o0 = e.x * sigmoidf_(v0 + bias[col]);
                    float o1 = e.y * sigmoidf_(v1 + bias[col + 1]);
                    *(float2*)(Ct + off) = make_float2(tf32r(o0), tf32r(o1));
                } else if (MODE == 3) {
                    *(float2*)(C + off) = make_float2(v0 + bias[col], v1 + bias[col + 1]);
                } else {  // MODE 4: interleaved gate pair
                    int j = col >> 1;
                    float g = (v0 + bias[j]) * sigmoidf_(v1 + bias2[j]);
                    size_t o = (size_t)row * HID + j;
                    C[o] = g;
                    Ct[o] = tf32r(g);
                }
            }
        }
    }
}

// ---------------- fused conv + SSM update + gated RMS norm -------------------
__global__ __launch_bounds__(256) void state_kernel(const float* __restrict__ conv_state,
                                                    const float* __restrict__ ssm_state,
                                                    const float* __restrict__ conv_w,
                                                    const float* __restrict__ conv_b,
                                                    const float* __restrict__ A_log,
                                                    const float* __restrict__ Dp,
                                                    const float* __restrict__ dt_bias,
                                                    const float* __restrict__ norm_w,
                                                    float* __restrict__ out_conv,
                                                    float* __restrict__ out_ssm) {
    int b = blockIdx.x, t = threadIdx.x;
    __shared__ __align__(16) float s_act[CONV_DIM];
    __shared__ float s_dt[NH], s_dA[NH], s_dp[NH];
    __shared__ __align__(16) float s_y[DIN];
    __shared__ float s_part[8][NG];
    __shared__ float s_gsum[NG];

    const float* zx = g_zx + (size_t)b * DINP_P;

    if (t < NH) {
        float d = zx[DIN + CONV_DIM + t] + dt_bias[t];
        float dt = (d > 20.f) ? d : log1pf(expf(d));
        s_dt[t] = dt;
        s_dA[t] = expf(-expf(A_log[t]) * dt);
        s_dp[t] = Dp[t];
    }

    for (int c = t; c < CONV_DIM; c += 256) {
        float4 cs = __ldcs((const float4*)(conv_state + ((size_t)b * CONV_DIM + c) * 4));
        float xv = zx[DIN + c];
        float4 w4 = *(const float4*)(conv_w + (size_t)c * 4);
        float4 nc = make_float4(cs.y, cs.z, cs.w, xv);
        __stcs((float4*)(out_conv + ((size_t)b * CONV_DIM + c) * 4), nc);
        float s = nc.x * w4.x + nc.y * w4.y + nc.z * w4.z + nc.w * w4.w + conv_b[c];
        s_act[c] = s / (1.f + expf(-s));
    }
    __syncthreads();

    int lane16 = t & 15;
    int half = t >> 4;
#pragma unroll 1
    for (int it = 0; it < DIN / 16; it++) {
        int rr = it * 16 + half;
        int h = rr >> 6, p = rr & 63, g = h >> 3;
        size_t base = (((size_t)b * NH + h) * HD + p) * DS + lane16 * 4;
        float4 sv = __ldcs((const float4*)(ssm_state + base));
        float4 B4 = *(const float4*)&s_act[DIN + g * DS + lane16 * 4];
        float4 C4 = *(const float4*)&s_act[DIN + NG * DS + g * DS + lane16 * 4];
        float xh = s_act[h * HD + p];
        float coef = s_dt[h] * xh;
        float dA = s_dA[h];
        float4 ns;
        ns.x = sv.x * dA + coef * B4.x;
        ns.y = sv.y * dA + coef * B4.y;
        ns.z = sv.z * dA + coef * B4.z;
        ns.w = sv.w * dA + coef * B4.w;
        __stcs((float4*)(out_ssm + base), ns);
        float part = ns.x * C4.x + ns.y * C4.y + ns.z * C4.z + ns.w * C4.w;
#pragma unroll
        for (int o = 8; o; o >>= 1) part += __shfl_xor_sync(0xffffffffu, part, o, 16);
        if (lane16 == 0) s_y[rr] = part + s_dp[h] * xh;
    }
    __syncthreads();

    float lsum[4] = {0.f, 0.f, 0.f, 0.f};
#pragma unroll
    for (int k = 0; k < 8; k++) {
        int d = t + k * 256;
        float z = zx[d];
        float yv = s_y[d] * (z / (1.f + expf(-z)));
        s_y[d] = yv;
        lsum[k >> 1] += yv * yv;
    }
    int wid = t >> 5, lane = t & 31;
#pragma unroll
    for (int gg = 0; gg < NG; gg++) {
        float v = lsum[gg];
#pragma unroll
        for (int o = 16; o; o >>= 1) v += __shfl_xor_sync(0xffffffffu, v, o);
        if (lane == 0) s_part[wid][gg] = v;
    }
    __syncthreads();
    if (t < NG) {
        float a = 0.f;
        for (int w = 0; w < 8; w++) a += s_part[w][t];
        s_gsum[t] = a;
    }
    __syncthreads();
#pragma unroll
    for (int k = 0; k < 8; k++) {
        int d = t + k * 256;
        float scale = rsqrtf(s_gsum[k >> 1] * (1.f / 512.f) + EPS);
        g_y_t[(size_t)b * DIN + d] = tf32r(s_y[d] * scale * norm_w[d]);
    }
}

// ---------------- launch ----------------------------------------------------
#define SMEM_BIG  (2 * (128 + 128) * 36 * 4)   // 73728
#define SMEM_MED  (2 * (128 + 64) * 36 * 4)    // 55296
#define SMEM_SML  (2 * (64 + 64) * 36 * 4)     // 36864

extern "C" void kernel_launch(void* const* d_in, const int* in_sizes, int n_in,
                              void* d_out, int out_size) {
    const float* frame_feat   = (const float*)d_in[0];
    const float* conv_state   = (const float*)d_in[1];
    const float* ssm_state    = (const float*)d_in[2];
    const float* ln_w         = (const float*)d_in[3];
    const float* ln_b         = (const float*)d_in[4];
    const float* w_in_gate    = (const float*)d_in[5];
    const float* b_in_gate    = (const float*)d_in[6];
    const float* w_input_proj = (const float*)d_in[7];
    const float* b_input_proj = (const float*)d_in[8];
    const float* w_in_proj    = (const float*)d_in[9];
    const float* conv_w       = (const float*)d_in[10];
    const float* conv_b       = (const float*)d_in[11];
    const float* A_log        = (const float*)d_in[12];
    const float* Dp           = (const float*)d_in[13];
    const float* dt_bias      = (const float*)d_in[14];
    const float* norm_w       = (const float*)d_in[15];
    const float* w_out_proj   = (const float*)d_in[16];
    const float* w_out_gate   = (const float*)d_in[17];
    const float* b_out_gate   = (const float*)d_in[18];
    const float* w_proj       = (const float*)d_in[19];
    const float* b_proj       = (const float*)d_in[20];

    float* out = (float*)d_out;
    float* out_clip = out;
    float* out_conv = out + (size_t)BATCH * CLIP_D;
    float* out_ssm = out_conv + (size_t)BATCH * CONV_DIM * DC;

    float *p_wcat, *p_winp, *p_wop, *p_wog, *p_wpj;
    float *p_xt, *p_gated, *p_gated_t, *p_zx, *p_yt, *p_op, *p_opt, *p_ot;
    cudaGetSymbolAddress((void**)&p_wcat, g_wcat);
    cudaGetSymbolAddress((void**)&p_winp, g_winproj_t);
    cudaGetSymbolAddress((void**)&p_wop, g_woutproj_t);
    cudaGetSymbolAddress((void**)&p_wog, g_woutgate_t);
    cudaGetSymbolAddress((void**)&p_wpj, g_wproj_t);
    cudaGetSymbolAddress((void**)&p_xt, g_x_t);
    cudaGetSymbolAddress((void**)&p_gated, g_gated);
    cudaGetSymbolAddress((void**)&p_gated_t, g_gated_t);
    cudaGetSymbolAddress((void**)&p_zx, g_zx);
    cudaGetSymbolAddress((void**)&p_yt, g_y_t);
    cudaGetSymbolAddress((void**)&p_op, g_outpre);
    cudaGetSymbolAddress((void**)&p_opt, g_outpre_t);
    cudaGetSymbolAddress((void**)&p_ot, g_out_t);

    cudaFuncSetAttribute((mma_gemm<4, 128, 128, 4, 4>), cudaFuncAttributeMaxDynamicSharedMemorySize, SMEM_BIG);
    cudaFuncSetAttribute((mma_gemm<0, 128, 128, 4, 4>), cudaFuncAttributeMaxDynamicSharedMemorySize, SMEM_BIG);
    cudaFuncSetAttribute((mma_gemm<1, 128, 64, 2, 4>), cudaFuncAttributeMaxDynamicSharedMemorySize, SMEM_MED);
    cudaFuncSetAttribute((mma_gemm<2, 128, 64, 2, 4>), cudaFuncAttributeMaxDynamicSharedMemorySize, SMEM_MED);
    cudaFuncSetAttribute((mma_gemm<3, 64, 64, 2, 2>), cudaFuncAttributeMaxDynamicSharedMemorySize, SMEM_SML);

    // 0) weight conversions (one launch)
    cvtall_k<<<(R_TOTAL + 255) / 256, 256>>>((const float4*)w_input_proj,
                                             (const float4*)w_in_gate,
                                             (const float4*)w_in_proj,
                                             (const float4*)w_out_proj,
                                             (const float4*)w_out_gate,
                                             (const float4*)w_proj);

    // 1) LayerNorm -> g_x_t (tf32)
    ln_kernel<<<BATCH, 256>>>(frame_feat, ln_w, ln_b);

    // 2) gate pair GEMM (BIG tile), interleaved epilogue -> g_gated / g_gated_t
    mma_gemm<4, 128, 128, 4, 4><<<dim3(2048 / 128, BATCH / 128), 256, SMEM_BIG>>>(
        p_xt, p_wcat, p_gated, p_gated_t, IN_DIM, 2048, b_input_proj, b_in_gate, nullptr);

    // 3) zx = gated @ w_in_proj^T (padded N) — big tile
    mma_gemm<0, 128, 128, 4, 4><<<dim3(DINP_P / 128, BATCH / 128), 256, SMEM_BIG>>>(
        p_gated_t, p_winp, p_zx, nullptr, HID, DINP_P, nullptr, nullptr, nullptr);

    // 4) conv + ssm + rmsnorm
    state_kernel<<<BATCH, 256>>>(conv_state, ssm_state, conv_w, conv_b,
                                 A_log, Dp, dt_bias, norm_w, out_conv, out_ssm);

    // 5) outpre = y @ w_out_proj^T + gated
    mma_gemm<1, 128, 64, 2, 4><<<dim3(HID / 64, BATCH / 128), 256, SMEM_MED>>>(
        p_yt, p_wop, p_op, p_opt, DIN, HID, nullptr, nullptr, p_gated);

    // 6) out = outpre * sigmoid(outpre @ w_out_gate^T + b)
    mma_gemm<2, 128, 64, 2, 4><<<dim3(HID / 64, BATCH / 128), 256, SMEM_MED>>>(
        p_opt, p_wog, nullptr, p_ot, HID, HID, b_out_gate, nullptr, p_op);

    // 7) clip = out @ w_proj^T + b
    mma_gemm<3, 64, 64, 2, 2><<<dim3(CLIP_D / 64, BATCH / 64), 256, SMEM_SML>>>(
        p_ot, p_wpj, out_clip, nullptr, HID, CLIP_D, b_proj, nullptr, nullptr);
}

// round 8
// speedup vs baseline: 1.9179x; 1.0152x over previous
#include <cuda_runtime.h>
#include <math.h>
#include <stdint.h>

#define BATCH 1024
#define IN_DIM 768
#define HID 1024
#define CLIP_D 512
#define NG 4
#define DS 64
#define DC 4
#define HD 64
#define DIN 2048
#define NH 32
#define CONV_DIM 2560
#define DINP 4640
#define DINP_P 4736
#define EPS 1e-5f

// ---------------- scratch (device globals) ----------------------------------
__device__ float g_wcat[2 * HID * IN_DIM];       // row-interleaved [wip_j; wig_j] tf32
__device__ float g_winproj_t[DINP_P * HID];
__device__ float g_woutproj_t[HID * DIN];
__device__ float g_woutgate_t[HID * HID];
__device__ float g_wproj_t[CLIP_D * HID];
__device__ float g_x_t[BATCH * IN_DIM];
__device__ float g_gated[BATCH * HID];
__device__ float g_gated_t[BATCH * HID];
__device__ float g_zx[BATCH * DINP_P];
__device__ float g_y_t[BATCH * DIN];
__device__ float g_outpre[BATCH * HID];
__device__ float g_outpre_t[BATCH * HID];
__device__ float g_out_t[BATCH * HID];

__device__ __forceinline__ float sigmoidf_(float x) { return 1.f / (1.f + expf(-x)); }
__device__ __forceinline__ float tf32r(float x) {
    uint32_t r;
    asm("cvt.rna.tf32.f32 %0, %1;" : "=r"(r) : "f"(x));
    return __uint_as_float(r);
}
__device__ __forceinline__ float4 tf32r4(float4 v) {
    return make_float4(tf32r(v.x), tf32r(v.y), tf32r(v.z), tf32r(v.w));
}

// ---------------- single fused weight-conversion kernel ----------------------
#define R_WCAT  393216                 // 2048*768/4 (row-interleaved)
#define R_WINP  1212416                // 4736*256
#define R_WOP   524288
#define R_WOG   262144
#define R_WPJ   131072
#define R_TOTAL (R_WCAT + R_WINP + R_WOP + R_WOG + R_WPJ)

__global__ __launch_bounds__(256) void cvtall_k(const float4* __restrict__ wip,
                                                const float4* __restrict__ wig,
                                                const float4* __restrict__ winp,
                                                const float4* __restrict__ wop,
                                                const float4* __restrict__ wog,
                                                const float4* __restrict__ wpj) {
    int i = blockIdx.x * 256 + threadIdx.x;
    if (i >= R_TOTAL) return;
    float4 v = make_float4(0.f, 0.f, 0.f, 0.f);
    float4* dst;
    if (i < R_WCAT) {
        dst = (float4*)g_wcat + i;
        int row = i / 192, col = i - row * 192;
        int sr = (row >> 1) * 192 + col;
        v = (row & 1) ? wig[sr] : wip[sr];
    } else if (i < R_WCAT + R_WINP) {
        int j = i - R_WCAT;
        dst = (float4*)g_winproj_t + j;
        if ((j >> 8) < DINP) v = winp[j];
    } else if (i < R_WCAT + R_WINP + R_WOP) {
        int j = i - R_WCAT - R_WINP;
        dst = (float4*)g_woutproj_t + j;
        v = wop[j];
    } else if (i < R_WCAT + R_WINP + R_WOP + R_WOG) {
        int j = i - R_WCAT - R_WINP - R_WOP;
        dst = (float4*)g_woutgate_t + j;
        v = wog[j];
    } else {
        int j = i - R_WCAT - R_WINP - R_WOP - R_WOG;
        dst = (float4*)g_wproj_t + j;
        v = wpj[j];
    }
    *dst = tf32r4(v);
}

// ---------------- LayerNorm -> tf32 ------------------------------------------
__global__ __launch_bounds__(256) void ln_kernel(const float* __restrict__ f,
                                                 const float* __restrict__ w,
                                                 const float* __restrict__ bb) {
    int b = blockIdx.x, t = threadIdx.x;
    const float* row = f + (size_t)b * IN_DIM;
    float s = 0.f, s2 = 0.f;
    for (int i = t; i < IN_DIM; i += 256) { float v = row[i]; s += v; s2 += v * v; }
#pragma unroll
    for (int o = 16; o; o >>= 1) {
        s  += __shfl_xor_sync(0xffffffffu, s, o);
        s2 += __shfl_xor_sync(0xffffffffu, s2, o);
    }
    __shared__ float rs[8], rs2[8], stats[2];
    int wid = t >> 5, lane = t & 31;
    if (lane == 0) { rs[wid] = s; rs2[wid] = s2; }
    __syncthreads();
    if (t == 0) {
        float a = 0.f, a2 = 0.f;
        for (int i = 0; i < 8; i++) { a += rs[i]; a2 += rs2[i]; }
        float mu = a / IN_DIM;
        float var = a2 / IN_DIM - mu * mu;
        stats[0] = mu;
        stats[1] = rsqrtf(var + EPS);
    }
    __syncthreads();
    float mu = stats[0], inv = stats[1];
    for (int i = t; i < IN_DIM; i += 256)
        g_x_t[(size_t)b * IN_DIM + i] = tf32r((row[i] - mu) * inv * w[i] + bb[i]);
}

// ---------------- tf32 tensor-core GEMM with ldmatrix ------------------------
// C[M,N] = A[M,K] @ B[N,K]^T.  2-stage cp.async, BK=32.
// NWARP*32 threads. warps_m = BM/(16*MI); warps_n = NWARP/warps_m = BN/(8*NI).
// A fragments: ldmatrix.x4 ; B fragments: pairwise ldmatrix.x4 (NI even).
#define CP16(dst_s, src_g) \
    asm volatile("cp.async.cg.shared.global [%0], [%1], 16;" :: "r"(dst_s), "l"(src_g))

__device__ __forceinline__ void ldsm_x4(uint32_t* f, uint32_t a) {
    asm volatile("ldmatrix.sync.aligned.m8n8.x4.shared.b16 {%0,%1,%2,%3}, [%4];"
                 : "=r"(f[0]), "=r"(f[1]), "=r"(f[2]), "=r"(f[3]) : "r"(a));
}

template <int MODE, int BM, int BN, int MI, int NI, int NWARP>
__global__ __launch_bounds__(NWARP * 32, 2) void mma_gemm(const float* __restrict__ A,
                                                          const float* __restrict__ Bm,
                                                          float* __restrict__ C,
                                                          float* __restrict__ Ct,
                                                          int K, int N,
                                                          const float* __restrict__ bias,
                                                          const float* __restrict__ bias2,
                                                          const float* __restrict__ extra) {
    constexpr int WMC = BM / (16 * MI);           // warps along M
    constexpr int STG = (BM + BN) * 36;           // floats per stage
    constexpr int NTHR = NWARP * 32;

    extern __shared__ float sm[];
    const int tid = threadIdx.x, lane = tid & 31, wid = tid >> 5;
    const int r = lane >> 2, cl = lane & 3;
    const int MOFF = (wid % WMC) * MI * 16;
    const int NOFF = (wid / WMC) * NI * 8;
    const int m0 = blockIdx.y * BM, n0 = blockIdx.x * BN;
    const int iters = K >> 5;

    float acc[MI][NI][4];
#pragma unroll
    for (int mi = 0; mi < MI; mi++)
#pragma unroll
        for (int ni = 0; ni < NI; ni++)
#pragma unroll
            for (int j = 0; j < 4; j++) acc[mi][ni][j] = 0.f;

    // per-lane ldmatrix byte offsets relative to stage base
    const uint32_t sbase = (uint32_t)__cvta_generic_to_shared(sm);
    uint32_t a_off[MI], b_off[NI / 2];
    {
        int am = lane >> 3, ai = lane & 7;
#pragma unroll
        for (int mi = 0; mi < MI; mi++)
            a_off[mi] = ((MOFF + mi * 16 + (am & 1) * 8 + ai) * 36 + (am >> 1) * 4) * 4;
        int bh = (lane >> 4) & 1;        // which n8 of the pair
        int bk = (lane >> 3) & 1;        // k half
        int bi = lane & 7;
#pragma unroll
        for (int j = 0; j < NI / 2; j++)
            b_off[j] = ((BM + NOFF + j * 16 + bh * 8 + bi) * 36 + bk * 4) * 4;
    }

    auto load_tile = [&](int s, int kt) {
        float* base = sm + s * STG;
        int k0 = kt << 5;
#pragma unroll
        for (int it = 0; it < (BM + BN) * 8 / NTHR; it++) {
            int task = tid + it * NTHR;
            int row = task >> 3, seg = (task & 7) << 2;
            const float* src = (row < BM)
                ? A + (size_t)(m0 + row) * K + k0 + seg
                : Bm + (size_t)(n0 + row - BM) * K + k0 + seg;
            uint32_t d = (uint32_t)__cvta_generic_to_shared(base + row * 36 + seg);
            CP16(d, src);
        }
        asm volatile("cp.async.commit_group;");
    };

    load_tile(0, 0);

    for (int kt = 0; kt < iters; kt++) {
        if (kt + 1 < iters) {
            load_tile((kt + 1) & 1, kt + 1);
            asm volatile("cp.async.wait_group 1;" ::: "memory");
        } else {
            asm volatile("cp.async.wait_group 0;" ::: "memory");
        }
        __syncthreads();

        const uint32_t stage = sbase + (uint32_t)((kt & 1) * STG * 4);
#pragma unroll
        for (int kk = 0; kk < 4; kk++) {
            uint32_t af[MI][4], bf[NI][2];
#pragma unroll
            for (int mi = 0; mi < MI; mi++)
                ldsm_x4(af[mi], stage + a_off[mi] + kk * 32);
#pragma unroll
            for (int j = 0; j < NI / 2; j++) {
                uint32_t tmp[4];
                ldsm_x4(tmp, stage + b_off[j] + kk * 32);
                bf[2 * j][0] = tmp[0]; bf[2 * j][1] = tmp[1];
                bf[2 * j + 1][0] = tmp[2]; bf[2 * j + 1][1] = tmp[3];
            }
#pragma unroll
            for (int mi = 0; mi < MI; mi++)
#pragma unroll
                for (int ni = 0; ni < NI; ni++) {
                    asm volatile(
                        "mma.sync.aligned.m16n8k8.row.col.f32.tf32.tf32.f32 "
                        "{%0,%1,%2,%3}, {%4,%5,%6,%7}, {%8,%9}, {%0,%1,%2,%3};"
                        : "+f"(acc[mi][ni][0]), "+f"(acc[mi][ni][1]),
                          "+f"(acc[mi][ni][2]), "+f"(acc[mi][ni][3])
                        : "r"(af[mi][0]), "r"(af[mi][1]), "r"(af[mi][2]), "r"(af[mi][3]),
                          "r"(bf[ni][0]), "r"(bf[ni][1]));
                }
        }
        __syncthreads();
    }

    // epilogue
#pragma unroll
    for (int mi = 0; mi < MI; mi++) {
        int row0 = m0 + MOFF + mi * 16 + r;
#pragma unroll
        for (int ni = 0; ni < NI; ni++) {
            int col = n0 + NOFF + ni * 8 + 2 * cl;
#pragma unroll
            for (int half = 0; half < 2; half++) {
                int row = row0 + half * 8;
                float v0 = acc[mi][ni][half * 2];
                float v1 = acc[mi][ni][half * 2 + 1];
                size_t off = (size_t)row * N + col;
                if (MODE == 0) {
                    *(float2*)(C + off) = make_float2(v0, v1);
                } else if (MODE == 1) {
                    float2 e = *(const float2*)(extra + off);
                    v0 += e.x; v1 += e.y;
                    *(float2*)(C + off) = make_float2(v0, v1);
                    *(float2*)(Ct + off) = make_float2(tf32r(v0), tf32r(v1));
                } else if (MODE == 2) {
                    float2 e = *(const float2*)(extra + off);
                    float o0 = e.x * sigmoidf_(v0 + bias[col]);
                    float o1 = e.y * sigmoidf_(v1 + bias[col + 1]);
                    *(float2*)(Ct + off) = make_float2(tf32r(o0), tf32r(o1));
                } else if (MODE == 3) {
                    *(float2*)(C + off) = make_float2(v0 + bias[col], v1 + bias[col + 1]);
                } else {  // MODE 4: interleaved gate pair
                    int j = col >> 1;
                    float g = (v0 + bias[j]) * sigmoidf_(v1 + bias2[j]);
                    size_t o = (size_t)row * HID + j;
                    C[o] = g;
                    Ct[o] = tf32r(g);
                }
            }
        }
    }
}

// ---------------- fused conv + SSM update + gated RMS norm -------------------
__global__ __launch_bounds__(256) void state_kernel(const float* __restrict__ conv_state,
                                                    const float* __restrict__ ssm_state,
                                                    const float* __restrict__ conv_w,
                                                    const float* __restrict__ conv_b,
                                                    const float* __restrict__ A_log,
                                                    const float* __restrict__ Dp,
                                                    const float* __restrict__ dt_bias,
                                                    const float* __restrict__ norm_w,
                                                    float* __restrict__ out_conv,
                                                    float* __restrict__ out_ssm) {
    int b = blockIdx.x, t = threadIdx.x;
    __shared__ __align__(16) float s_act[CONV_DIM];
    __shared__ float s_dt[NH], s_dA[NH], s_dp[NH];
    __shared__ __align__(16) float s_y[DIN];
    __shared__ float s_part[8][NG];
    __shared__ float s_gsum[NG];

    const float* zx = g_zx + (size_t)b * DINP_P;

    if (t < NH) {
        float d = zx[DIN + CONV_DIM + t] + dt_bias[t];
        float dt = (d > 20.f) ? d : log1pf(expf(d));
        s_dt[t] = dt;
        s_dA[t] = expf(-expf(A_log[t]) * dt);
        s_dp[t] = Dp[t];
    }

    for (int c = t; c < CONV_DIM; c += 256) {
        float4 cs = __ldcs((const float4*)(conv_state + ((size_t)b * CONV_DIM + c) * 4));
        float xv = zx[DIN + c];
        float4 w4 = *(const float4*)(conv_w + (size_t)c * 4);
        float4 nc = make_float4(cs.y, cs.z, cs.w, xv);
        __stcs((float4*)(out_conv + ((size_t)b * CONV_DIM + c) * 4), nc);
        float s = nc.x * w4.x + nc.y * w4.y + nc.z * w4.z + nc.w * w4.w + conv_b[c];
        s_act[c] = s / (1.f + expf(-s));
    }
    __syncthreads();

    int lane16 = t & 15;
    int half = t >> 4;
#pragma unroll 1
    for (int it = 0; it < DIN / 16; it++) {
        int rr = it * 16 + half;
        int h = rr >> 6, p = rr & 63, g = h >> 3;
        size_t base = (((size_t)b * NH + h) * HD + p) * DS + lane16 * 4;
        float4 sv = __ldcs((const float4*)(ssm_state + base));
        float4 B4 = *(const float4*)&s_act[DIN + g * DS + lane16 * 4];
        float4 C4 = *(const float4*)&s_act[DIN + NG * DS + g * DS + lane16 * 4];
        float xh = s_act[h * HD + p];
        float coef = s_dt[h] * xh;
        float dA = s_dA[h];
        float4 ns;
        ns.x = sv.x * dA + coef * B4.x;
        ns.y = sv.y * dA + coef * B4.y;
        ns.z = sv.z * dA + coef * B4.z;
        ns.w = sv.w * dA + coef * B4.w;
        __stcs((float4*)(out_ssm + base), ns);
        float part = ns.x * C4.x + ns.y * C4.y + ns.z * C4.z + ns.w * C4.w;
#pragma unroll
        for (int o = 8; o; o >>= 1) part += __shfl_xor_sync(0xffffffffu, part, o, 16);
        if (lane16 == 0) s_y[rr] = part + s_dp[h] * xh;
    }
    __syncthreads();

    float lsum[4] = {0.f, 0.f, 0.f, 0.f};
#pragma unroll
    for (int k = 0; k < 8; k++) {
        int d = t + k * 256;
        float z = zx[d];
        float yv = s_y[d] * (z / (1.f + expf(-z)));
        s_y[d] = yv;
        lsum[k >> 1] += yv * yv;
    }
    int wid = t >> 5, lane = t & 31;
#pragma unroll
    for (int gg = 0; gg < NG; gg++) {
        float v = lsum[gg];
#pragma unroll
        for (int o = 16; o; o >>= 1) v += __shfl_xor_sync(0xffffffffu, v, o);
        if (lane == 0) s_part[wid][gg] = v;
    }
    __syncthreads();
    if (t < NG) {
        float a = 0.f;
        for (int w = 0; w < 8; w++) a += s_part[w][t];
        s_gsum[t] = a;
    }
    __syncthreads();
#pragma unroll
    for (int k = 0; k < 8; k++) {
        int d = t + k * 256;
        float scale = rsqrtf(s_gsum[k >> 1] * (1.f / 512.f) + EPS);
        g_y_t[(size_t)b * DIN + d] = tf32r(s_y[d] * scale * norm_w[d]);
    }
}

// ---------------- launch ----------------------------------------------------
#define SMEM_BIG  (2 * (128 + 128) * 36 * 4)   // 73728
#define SMEM_MED  (2 * (128 + 64) * 36 * 4)    // 55296
#define SMEM_SML  (2 * (64 + 64) * 36 * 4)     // 36864

extern "C" void kernel_launch(void* const* d_in, const int* in_sizes, int n_in,
                              void* d_out, int out_size) {
    const float* frame_feat   = (const float*)d_in[0];
    const float* conv_state   = (const float*)d_in[1];
    const float* ssm_state    = (const float*)d_in[2];
    const float* ln_w         = (const float*)d_in[3];
    const float* ln_b         = (const float*)d_in[4];
    const float* w_in_gate    = (const float*)d_in[5];
    const float* b_in_gate    = (const float*)d_in[6];
    const float* w_input_proj = (const float*)d_in[7];
    const float* b_input_proj = (const float*)d_in[8];
    const float* w_in_proj    = (const float*)d_in[9];
    const float* conv_w       = (const float*)d_in[10];
    const float* conv_b       = (const float*)d_in[11];
    const float* A_log        = (const float*)d_in[12];
    const float* Dp           = (const float*)d_in[13];
    const float* dt_bias      = (const float*)d_in[14];
    const float* norm_w       = (const float*)d_in[15];
    const float* w_out_proj   = (const float*)d_in[16];
    const float* w_out_gate   = (const float*)d_in[17];
    const float* b_out_gate   = (const float*)d_in[18];
    const float* w_proj       = (const float*)d_in[19];
    const float* b_proj       = (const float*)d_in[20];

    float* out = (float*)d_out;
    float* out_clip = out;
    float* out_conv = out + (size_t)BATCH * CLIP_D;
    float* out_ssm = out_conv + (size_t)BATCH * CONV_DIM * DC;

    float *p_wcat, *p_winp, *p_wop, *p_wog, *p_wpj;
    float *p_xt, *p_gated, *p_gated_t, *p_zx, *p_yt, *p_op, *p_opt, *p_ot;
    cudaGetSymbolAddress((void**)&p_wcat, g_wcat);
    cudaGetSymbolAddress((void**)&p_winp, g_winproj_t);
    cudaGetSymbolAddress((void**)&p_wop, g_woutproj_t);
    cudaGetSymbolAddress((void**)&p_wog, g_woutgate_t);
    cudaGetSymbolAddress((void**)&p_wpj, g_wproj_t);
    cudaGetSymbolAddress((void**)&p_xt, g_x_t);
    cudaGetSymbolAddress((void**)&p_gated, g_gated);
    cudaGetSymbolAddress((void**)&p_gated_t, g_gated_t);
    cudaGetSymbolAddress((void**)&p_zx, g_zx);
    cudaGetSymbolAddress((void**)&p_yt, g_y_t);
    cudaGetSymbolAddress((void**)&p_op, g_outpre);
    cudaGetSymbolAddress((void**)&p_opt, g_outpre_t);
    cudaGetSymbolAddress((void**)&p_ot, g_out_t);

    cudaFuncSetAttribute((mma_gemm<4, 128, 128, 4, 4, 8>), cudaFuncAttributeMaxDynamicSharedMemorySize, SMEM_BIG);
    cudaFuncSetAttribute((mma_gemm<0, 128, 128, 4, 8, 4>), cudaFuncAttributeMaxDynamicSharedMemorySize, SMEM_BIG);
    cudaFuncSetAttribute((mma_gemm<1, 128, 64, 2, 4, 8>), cudaFuncAttributeMaxDynamicSharedMemorySize, SMEM_MED);
    cudaFuncSetAttribute((mma_gemm<2, 128, 64, 2, 4, 8>), cudaFuncAttributeMaxDynamicSharedMemorySize, SMEM_MED);
    cudaFuncSetAttribute((mma_gemm<3, 64, 64, 2, 2, 8>), cudaFuncAttributeMaxDynamicSharedMemorySize, SMEM_SML);

    // 0) weight conversions (one launch)
    cvtall_k<<<(R_TOTAL + 255) / 256, 256>>>((const float4*)w_input_proj,
                                             (const float4*)w_in_gate,
                                             (const float4*)w_in_proj,
                                             (const float4*)w_out_proj,
                                             (const float4*)w_out_gate,
                                             (const float4*)w_proj);

    // 1) LayerNorm -> g_x_t (tf32)
    ln_kernel<<<BATCH, 256>>>(frame_feat, ln_w, ln_b);

    // 2) gate pair GEMM (BIG tile, 8 warps), interleaved epilogue
    mma_gemm<4, 128, 128, 4, 4, 8><<<dim3(2048 / 128, BATCH / 128), 256, SMEM_BIG>>>(
        p_xt, p_wcat, p_gated, p_gated_t, IN_DIM, 2048, b_input_proj, b_in_gate, nullptr);

    // 3) zx = gated @ w_in_proj^T (padded N) — BIG tile, 4 warps (64x64 warp tile)
    mma_gemm<0, 128, 128, 4, 8, 4><<<dim3(DINP_P / 128, BATCH / 128), 128, SMEM_BIG>>>(
        p_gated_t, p_winp, p_zx, nullptr, HID, DINP_P, nullptr, nullptr, nullptr);

    // 4) conv + ssm + rmsnorm
    state_kernel<<<BATCH, 256>>>(conv_state, ssm_state, conv_w, conv_b,
                                 A_log, Dp, dt_bias, norm_w, out_conv, out_ssm);

    // 5) outpre = y @ w_out_proj^T + gated
    mma_gemm<1, 128, 64, 2, 4, 8><<<dim3(HID / 64, BATCH / 128), 256, SMEM_MED>>>(
        p_yt, p_wop, p_op, p_opt, DIN, HID, nullptr, nullptr, p_gated);

    // 6) out = outpre * sigmoid(outpre @ w_out_gate^T + b)
    mma_gemm<2, 128, 64, 2, 4, 8><<<dim3(HID / 64, BATCH / 128), 256, SMEM_MED>>>(
        p_opt, p_wog, nullptr, p_ot, HID, HID, b_out_gate, nullptr, p_op);

    // 7) clip = out @ w_proj^T + b
    mma_gemm<3, 64, 64, 2, 2, 8><<<dim3(CLIP_D / 64, BATCH / 64), 256, SMEM_SML>>>(
        p_ot, p_wpj, out_clip, nullptr, HID, CLIP_D, b_proj, nullptr, nullptr);
}

// round 9
// speedup vs baseline: 2.0762x; 1.0826x over previous
#include <cuda_runtime.h>
#include <math.h>
#include <stdint.h>

#define BATCH 1024
#define IN_DIM 768
#define HID 1024
#define CLIP_D 512
#define NG 4
#define DS 64
#define DC 4
#define HD 64
#define DIN 2048
#define NH 32
#define CONV_DIM 2560
#define DINP 4640
#define DINP_P 4736
#define EPS 1e-5f

// ---------------- scratch (device globals) ----------------------------------
__device__ float g_wcat[2 * HID * IN_DIM];       // row-interleaved [wip_j; wig_j] tf32
__device__ float g_winproj_t[DINP_P * HID];
__device__ float g_woutproj_t[HID * DIN];
__device__ float g_woutgate_t[HID * HID];
__device__ float g_wproj_t[CLIP_D * HID];
__device__ float g_x_t[BATCH * IN_DIM];
__device__ float g_gated[BATCH * HID];
__device__ float g_gated_t[BATCH * HID];
__device__ float g_zx[BATCH * DINP_P];
__device__ float g_y_t[BATCH * DIN];
__device__ float g_outpre[BATCH * HID];
__device__ float g_outpre_t[BATCH * HID];
__device__ float g_out_t[BATCH * HID];

__device__ __forceinline__ float sigmoidf_(float x) { return 1.f / (1.f + expf(-x)); }
__device__ __forceinline__ float tf32r(float x) {
    uint32_t r;
    asm("cvt.rna.tf32.f32 %0, %1;" : "=r"(r) : "f"(x));
    return __uint_as_float(r);
}
__device__ __forceinline__ float4 tf32r4(float4 v) {
    return make_float4(tf32r(v.x), tf32r(v.y), tf32r(v.z), tf32r(v.w));
}

// ---------------- single fused weight-conversion kernel ----------------------
#define R_WCAT  393216                 // 2048*768/4 (row-interleaved)
#define R_WINP  1212416                // 4736*256
#define R_WOP   524288
#define R_WOG   262144
#define R_WPJ   131072
#define R_TOTAL (R_WCAT + R_WINP + R_WOP + R_WOG + R_WPJ)

__global__ __launch_bounds__(256) void cvtall_k(const float4* __restrict__ wip,
                                                const float4* __restrict__ wig,
                                                const float4* __restrict__ winp,
                                                const float4* __restrict__ wop,
                                                const float4* __restrict__ wog,
                                                const float4* __restrict__ wpj) {
    int i = blockIdx.x * 256 + threadIdx.x;
    if (i >= R_TOTAL) return;
    float4 v = make_float4(0.f, 0.f, 0.f, 0.f);
    float4* dst;
    if (i < R_WCAT) {
        dst = (float4*)g_wcat + i;
        int row = i / 192, col = i - row * 192;
        int sr = (row >> 1) * 192 + col;
        v = (row & 1) ? wig[sr] : wip[sr];
    } else if (i < R_WCAT + R_WINP) {
        int j = i - R_WCAT;
        dst = (float4*)g_winproj_t + j;
        if ((j >> 8) < DINP) v = winp[j];
    } else if (i < R_WCAT + R_WINP + R_WOP) {
        int j = i - R_WCAT - R_WINP;
        dst = (float4*)g_woutproj_t + j;
        v = wop[j];
    } else if (i < R_WCAT + R_WINP + R_WOP + R_WOG) {
        int j = i - R_WCAT - R_WINP - R_WOP;
        dst = (float4*)g_woutgate_t + j;
        v = wog[j];
    } else {
        int j = i - R_WCAT - R_WINP - R_WOP - R_WOG;
        dst = (float4*)g_wproj_t + j;
        v = wpj[j];
    }
    *dst = tf32r4(v);
}

// ---------------- LayerNorm -> tf32 ------------------------------------------
__global__ __launch_bounds__(256) void ln_kernel(const float* __restrict__ f,
                                                 const float* __restrict__ w,
                                                 const float* __restrict__ bb) {
    int b = blockIdx.x, t = threadIdx.x;
    const float* row = f + (size_t)b * IN_DIM;
    float s = 0.f, s2 = 0.f;
    for (int i = t; i < IN_DIM; i += 256) { float v = row[i]; s += v; s2 += v * v; }
#pragma unroll
    for (int o = 16; o; o >>= 1) {
        s  += __shfl_xor_sync(0xffffffffu, s, o);
        s2 += __shfl_xor_sync(0xffffffffu, s2, o);
    }
    __shared__ float rs[8], rs2[8], stats[2];
    int wid = t >> 5, lane = t & 31;
    if (lane == 0) { rs[wid] = s; rs2[wid] = s2; }
    __syncthreads();
    if (t == 0) {
        float a = 0.f, a2 = 0.f;
        for (int i = 0; i < 8; i++) { a += rs[i]; a2 += rs2[i]; }
        float mu = a / IN_DIM;
        float var = a2 / IN_DIM - mu * mu;
        stats[0] = mu;
        stats[1] = rsqrtf(var + EPS);
    }
    __syncthreads();
    float mu = stats[0], inv = stats[1];
    for (int i = t; i < IN_DIM; i += 256)
        g_x_t[(size_t)b * IN_DIM + i] = tf32r((row[i] - mu) * inv * w[i] + bb[i]);
}

// ---------------- tf32 tensor-core GEMM: swizzled smem, 3-stage --------------
// C[M,N] = A[M,K] @ B[N,K]^T.  BK=32, XOR-swizzle (seg ^= row&7), ldmatrix.
#define CP16(dst_s, src_g) \
    asm volatile("cp.async.cg.shared.global [%0], [%1], 16;" :: "r"(dst_s), "l"(src_g))

__device__ __forceinline__ void ldsm_x4(uint32_t* f, uint32_t a) {
    asm volatile("ldmatrix.sync.aligned.m8n8.x4.shared.b16 {%0,%1,%2,%3}, [%4];"
                 : "=r"(f[0]), "=r"(f[1]), "=r"(f[2]), "=r"(f[3]) : "r"(a));
}

template <int MODE, int BM, int BN, int MI, int NI, int NWARP>
__global__ __launch_bounds__(NWARP * 32, 2) void mma_gemm(const float* __restrict__ A,
                                                          const float* __restrict__ Bm,
                                                          float* __restrict__ C,
                                                          float* __restrict__ Ct,
                                                          int K, int N,
                                                          const float* __restrict__ bias,
                                                          const float* __restrict__ bias2,
                                                          const float* __restrict__ extra) {
    constexpr int WMC = BM / (16 * MI);           // warps along M
    constexpr int STG = (BM + BN) * 32;           // floats per stage (swizzled, no pad)
    constexpr int NTHR = NWARP * 32;

    extern __shared__ float sm[];
    const int tid = threadIdx.x, lane = tid & 31, wid = tid >> 5;
    const int r = lane >> 2, cl = lane & 3;
    const int MOFF = (wid % WMC) * MI * 16;
    const int NOFF = (wid / WMC) * NI * 8;
    const int m0 = blockIdx.y * BM, n0 = blockIdx.x * BN;
    const int iters = K >> 5;

    float acc[MI][NI][4];
#pragma unroll
    for (int mi = 0; mi < MI; mi++)
#pragma unroll
        for (int ni = 0; ni < NI; ni++)
#pragma unroll
            for (int j = 0; j < 4; j++) acc[mi][ni][j] = 0.f;

    // per-lane ldmatrix swizzle state (byte base + row&7 + k-half)
    const uint32_t sbase = (uint32_t)__cvta_generic_to_shared(sm);
    uint32_t a_base[MI], b_base[NI / 2];
    uint32_t a_r7[MI], b_r7[NI / 2];
    uint32_t a_kh, b_kh;
    {
        int am = lane >> 3, ai = lane & 7;
        a_kh = am >> 1;
#pragma unroll
        for (int mi = 0; mi < MI; mi++) {
            int row = MOFF + mi * 16 + (am & 1) * 8 + ai;
            a_base[mi] = (uint32_t)row * 128;       // row * 32 floats * 4 B
            a_r7[mi] = row & 7;
        }
        int bh = (lane >> 4) & 1, bk = (lane >> 3) & 1, bi = lane & 7;
        b_kh = bk;
#pragma unroll
        for (int j = 0; j < NI / 2; j++) {
            int row = BM + NOFF + j * 16 + bh * 8 + bi;
            b_base[j] = (uint32_t)row * 128;
            b_r7[j] = row & 7;
        }
    }

    auto load_tile = [&](int s, int kt) {
        float* base = sm + s * STG;
        int k0 = kt << 5;
#pragma unroll
        for (int it = 0; it < (BM + BN) * 8 / NTHR; it++) {
            int task = tid + it * NTHR;
            int row = task >> 3, seg = task & 7;
            const float* src = (row < BM)
                ? A + (size_t)(m0 + row) * K + k0 + (seg << 2)
                : Bm + (size_t)(n0 + row - BM) * K + k0 + (seg << 2);
            int ps = seg ^ (row & 7);
            uint32_t d = (uint32_t)__cvta_generic_to_shared(base + row * 32 + (ps << 2));
            CP16(d, src);
        }
        asm volatile("cp.async.commit_group;");
    };

    load_tile(0, 0);
    load_tile(1, 1);

    int s_cur = 0, s_nxt = 2;
    for (int kt = 0; kt < iters; kt++) {
        asm volatile("cp.async.wait_group 1;" ::: "memory");
        __syncthreads();
        if (kt + 2 < iters) load_tile(s_nxt, kt + 2);
        else asm volatile("cp.async.commit_group;");

        const uint32_t stage = sbase + (uint32_t)(s_cur * STG * 4);
#pragma unroll
        for (int kk = 0; kk < 4; kk++) {
            uint32_t af[MI][4], bf[NI][2];
#pragma unroll
            for (int mi = 0; mi < MI; mi++)
                ldsm_x4(af[mi], stage + a_base[mi] + ((((uint32_t)kk * 2 + a_kh) ^ a_r7[mi]) << 4));
#pragma unroll
            for (int j = 0; j < NI / 2; j++) {
                uint32_t tmp[4];
                ldsm_x4(tmp, stage + b_base[j] + ((((uint32_t)kk * 2 + b_kh) ^ b_r7[j]) << 4));
                bf[2 * j][0] = tmp[0]; bf[2 * j][1] = tmp[1];
                bf[2 * j + 1][0] = tmp[2]; bf[2 * j + 1][1] = tmp[3];
            }
#pragma unroll
            for (int mi = 0; mi < MI; mi++)
#pragma unroll
                for (int ni = 0; ni < NI; ni++) {
                    asm volatile(
                        "mma.sync.aligned.m16n8k8.row.col.f32.tf32.tf32.f32 "
                        "{%0,%1,%2,%3}, {%4,%5,%6,%7}, {%8,%9}, {%0,%1,%2,%3};"
                        : "+f"(acc[mi][ni][0]), "+f"(acc[mi][ni][1]),
                          "+f"(acc[mi][ni][2]), "+f"(acc[mi][ni][3])
                        : "r"(af[mi][0]), "r"(af[mi][1]), "r"(af[mi][2]), "r"(af[mi][3]),
                          "r"(bf[ni][0]), "r"(bf[ni][1]));
                }
        }
        s_cur = (s_cur == 2) ? 0 : s_cur + 1;
        s_nxt = (s_nxt == 2) ? 0 : s_nxt + 1;
    }

    // epilogue
#pragma unroll
    for (int mi = 0; mi < MI; mi++) {
        int row0 = m0 + MOFF + mi * 16 + r;
#pragma unroll
        for (int ni = 0; ni < NI; ni++) {
            int col = n0 + NOFF + ni * 8 + 2 * cl;
#pragma unroll
            for (int half = 0; half < 2; half++) {
                int row = row0 + half * 8;
                float v0 = acc[mi][ni][half * 2];
                float v1 = acc[mi][ni][half * 2 + 1];
                size_t off = (size_t)row * N + col;
                if (MODE == 0) {
                    *(float2*)(C + off) = make_float2(v0, v1);
                } else if (MODE == 1) {
                    float2 e = *(const float2*)(extra + off);
                    v0 += e.x; v1 += e.y;
                    *(float2*)(C + off) = make_float2(v0, v1);
                    *(float2*)(Ct + off) = make_float2(tf32r(v0), tf32r(v1));
                } else if (MODE == 2) {
                    float2 e = *(const float2*)(extra + off);
                    float o0 = e.x * sigmoidf_(v0 + bias[col]);
                    float o1 = e.y * sigmoidf_(v1 + bias[col + 1]);
                    *(float2*)(Ct + off) = make_float2(tf32r(o0), tf32r(o1));
                } else if (MODE == 3) {
                    *(float2*)(C + off) = make_float2(v0 + bias[col], v1 + bias[col + 1]);
                } else {  // MODE 4: interleaved gate pair
                    int j = col >> 1;
                    float g = (v0 + bias[j]) * sigmoidf_(v1 + bias2[j]);
                    size_t o = (size_t)row * HID + j;
                    C[o] = g;
                    Ct[o] = tf32r(g);
                }
            }
        }
    }
}

// ---------------- fused conv + SSM update + gated RMS norm -------------------
__global__ __launch_bounds__(256) void state_kernel(const float* __restrict__ conv_state,
                                                    const float* __restrict__ ssm_state,
                                                    const float* __restrict__ conv_w,
                                                    const float* __restrict__ conv_b,
                                                    const float* __restrict__ A_log,
                                                    const float* __restrict__ Dp,
                                                    const float* __restrict__ dt_bias,
                                                    const float* __restrict__ norm_w,
                                                    float* __restrict__ out_conv,
                                                    float* __restrict__ out_ssm) {
    int b = blockIdx.x, t = threadIdx.x;
    __shared__ __align__(16) float s_act[CONV_DIM];
    __shared__ float s_dt[NH], s_dA[NH], s_dp[NH];
    __shared__ __align__(16) float s_y[DIN];
    __shared__ float s_part[8][NG];
    __shared__ float s_gsum[NG];

    const float* zx = g_zx + (size_t)b * DINP_P;

    if (t < NH) {
        float d = zx[DIN + CONV_DIM + t] + dt_bias[t];
        float dt = (d > 20.f) ? d : log1pf(expf(d));
        s_dt[t] = dt;
        s_dA[t] = expf(-expf(A_log[t]) * dt);
        s_dp[t] = Dp[t];
    }

    for (int c = t; c < CONV_DIM; c += 256) {
        float4 cs = __ldcs((const float4*)(conv_state + ((size_t)b * CONV_DIM + c) * 4));
        float xv = zx[DIN + c];
        float4 w4 = *(const float4*)(conv_w + (size_t)c * 4);
        float4 nc = make_float4(cs.y, cs.z, cs.w, xv);
        __stcs((float4*)(out_conv + ((size_t)b * CONV_DIM + c) * 4), nc);
        float s = nc.x * w4.x + nc.y * w4.y + nc.z * w4.z + nc.w * w4.w + conv_b[c];
        s_act[c] = s / (1.f + expf(-s));
    }
    __syncthreads();

    int lane16 = t & 15;
    int half = t >> 4;
#pragma unroll 1
    for (int it = 0; it < DIN / 16; it++) {
        int rr = it * 16 + half;
        int h = rr >> 6, p = rr & 63, g = h >> 3;
        size_t base = (((size_t)b * NH + h) * HD + p) * DS + lane16 * 4;
        float4 sv = __ldcs((const float4*)(ssm_state + base));
        float4 B4 = *(const float4*)&s_act[DIN + g * DS + lane16 * 4];
        float4 C4 = *(const float4*)&s_act[DIN + NG * DS + g * DS + lane16 * 4];
        float xh = s_act[h * HD + p];
        float coef = s_dt[h] * xh;
        float dA = s_dA[h];
        float4 ns;
        ns.x = sv.x * dA + coef * B4.x;
        ns.y = sv.y * dA + coef * B4.y;
        ns.z = sv.z * dA + coef * B4.z;
        ns.w = sv.w * dA + coef * B4.w;
        __stcs((float4*)(out_ssm + base), ns);
        float part = ns.x * C4.x + ns.y * C4.y + ns.z * C4.z + ns.w * C4.w;
#pragma unroll
        for (int o = 8; o; o >>= 1) part += __shfl_xor_sync(0xffffffffu, part, o, 16);
        if (lane16 == 0) s_y[rr] = part + s_dp[h] * xh;
    }
    __syncthreads();

    float lsum[4] = {0.f, 0.f, 0.f, 0.f};
#pragma unroll
    for (int k = 0; k < 8; k++) {
        int d = t + k * 256;
        float z = zx[d];
        float yv = s_y[d] * (z / (1.f + expf(-z)));
        s_y[d] = yv;
        lsum[k >> 1] += yv * yv;
    }
    int wid = t >> 5, lane = t & 31;
#pragma unroll
    for (int gg = 0; gg < NG; gg++) {
        float v = lsum[gg];
#pragma unroll
        for (int o = 16; o; o >>= 1) v += __shfl_xor_sync(0xffffffffu, v, o);
        if (lane == 0) s_part[wid][gg] = v;
    }
    __syncthreads();
    if (t < NG) {
        float a = 0.f;
        for (int w = 0; w < 8; w++) a += s_part[w][t];
        s_gsum[t] = a;
    }
    __syncthreads();
#pragma unroll
    for (int k = 0; k < 8; k++) {
        int d = t + k * 256;
        float scale = rsqrtf(s_gsum[k >> 1] * (1.f / 512.f) + EPS);
        g_y_t[(size_t)b * DIN + d] = tf32r(s_y[d] * scale * norm_w[d]);
    }
}

// ---------------- launch ----------------------------------------------------
#define SMEM_BIG3 (3 * (128 + 128) * 32 * 4)   // 98304
#define SMEM_MED3 (3 * (128 + 64) * 32 * 4)    // 73728
#define SMEM_SML3 (3 * (64 + 64) * 32 * 4)     // 49152

extern "C" void kernel_launch(void* const* d_in, const int* in_sizes, int n_in,
                              void* d_out, int out_size) {
    const float* frame_feat   = (const float*)d_in[0];
    const float* conv_state   = (const float*)d_in[1];
    const float* ssm_state    = (const float*)d_in[2];
    const float* ln_w         = (const float*)d_in[3];
    const float* ln_b         = (const float*)d_in[4];
    const float* w_in_gate    = (const float*)d_in[5];
    const float* b_in_gate    = (const float*)d_in[6];
    const float* w_input_proj = (const float*)d_in[7];
    const float* b_input_proj = (const float*)d_in[8];
    const float* w_in_proj    = (const float*)d_in[9];
    const float* conv_w       = (const float*)d_in[10];
    const float* conv_b       = (const float*)d_in[11];
    const float* A_log        = (const float*)d_in[12];
    const float* Dp           = (const float*)d_in[13];
    const float* dt_bias      = (const float*)d_in[14];
    const float* norm_w       = (const float*)d_in[15];
    const float* w_out_proj   = (const float*)d_in[16];
    const float* w_out_gate   = (const float*)d_in[17];
    const float* b_out_gate   = (const float*)d_in[18];
    const float* w_proj       = (const float*)d_in[19];
    const float* b_proj       = (const float*)d_in[20];

    float* out = (float*)d_out;
    float* out_clip = out;
    float* out_conv = out + (size_t)BATCH * CLIP_D;
    float* out_ssm = out_conv + (size_t)BATCH * CONV_DIM * DC;

    float *p_wcat, *p_winp, *p_wop, *p_wog, *p_wpj;
    float *p_xt, *p_gated, *p_gated_t, *p_zx, *p_yt, *p_op, *p_opt, *p_ot;
    cudaGetSymbolAddress((void**)&p_wcat, g_wcat);
    cudaGetSymbolAddress((void**)&p_winp, g_winproj_t);
    cudaGetSymbolAddress((void**)&p_wop, g_woutproj_t);
    cudaGetSymbolAddress((void**)&p_wog, g_woutgate_t);
    cudaGetSymbolAddress((void**)&p_wpj, g_wproj_t);
    cudaGetSymbolAddress((void**)&p_xt, g_x_t);
    cudaGetSymbolAddress((void**)&p_gated, g_gated);
    cudaGetSymbolAddress((void**)&p_gated_t, g_gated_t);
    cudaGetSymbolAddress((void**)&p_zx, g_zx);
    cudaGetSymbolAddress((void**)&p_yt, g_y_t);
    cudaGetSymbolAddress((void**)&p_op, g_outpre);
    cudaGetSymbolAddress((void**)&p_opt, g_outpre_t);
    cudaGetSymbolAddress((void**)&p_ot, g_out_t);

    cudaFuncSetAttribute((mma_gemm<4, 128, 128, 4, 4, 8>), cudaFuncAttributeMaxDynamicSharedMemorySize, SMEM_BIG3);
    cudaFuncSetAttribute((mma_gemm<0, 128, 128, 4, 8, 4>), cudaFuncAttributeMaxDynamicSharedMemorySize, SMEM_BIG3);
    cudaFuncSetAttribute((mma_gemm<1, 128, 64, 2, 4, 8>), cudaFuncAttributeMaxDynamicSharedMemorySize, SMEM_MED3);
    cudaFuncSetAttribute((mma_gemm<2, 128, 64, 2, 4, 8>), cudaFuncAttributeMaxDynamicSharedMemorySize, SMEM_MED3);
    cudaFuncSetAttribute((mma_gemm<3, 64, 64, 2, 2, 8>), cudaFuncAttributeMaxDynamicSharedMemorySize, SMEM_SML3);

    // 0) weight conversions (one launch)
    cvtall_k<<<(R_TOTAL + 255) / 256, 256>>>((const float4*)w_input_proj,
                                             (const float4*)w_in_gate,
                                             (const float4*)w_in_proj,
                                             (const float4*)w_out_proj,
                                             (const float4*)w_out_gate,
                                             (const float4*)w_proj);

    // 1) LayerNorm -> g_x_t (tf32)
    ln_kernel<<<BATCH, 256>>>(frame_feat, ln_w, ln_b);

    // 2) gate pair GEMM (BIG tile, 8 warps), interleaved epilogue
    mma_gemm<4, 128, 128, 4, 4, 8><<<dim3(2048 / 128, BATCH / 128), 256, SMEM_BIG3>>>(
        p_xt, p_wcat, p_gated, p_gated_t, IN_DIM, 2048, b_input_proj, b_in_gate, nullptr);

    // 3) zx = gated @ w_in_proj^T (padded N) — BIG tile, 4 warps (64x64 warp tile)
    mma_gemm<0, 128, 128, 4, 8, 4><<<dim3(DINP_P / 128, BATCH / 128), 128, SMEM_BIG3>>>(
        p_gated_t, p_winp, p_zx, nullptr, HID, DINP_P, nullptr, nullptr, nullptr);

    // 4) conv + ssm + rmsnorm
    state_kernel<<<BATCH, 256>>>(conv_state, ssm_state, conv_w, conv_b,
                                 A_log, Dp, dt_bias, norm_w, out_conv, out_ssm);

    // 5) outpre = y @ w_out_proj^T + gated
    mma_gemm<1, 128, 64, 2, 4, 8><<<dim3(HID / 64, BATCH / 128), 256, SMEM_MED3>>>(
        p_yt, p_wop, p_op, p_opt, DIN, HID, nullptr, nullptr, p_gated);

    // 6) out = outpre * sigmoid(outpre @ w_out_gate^T + b)
    mma_gemm<2, 128, 64, 2, 4, 8><<<dim3(HID / 64, BATCH / 128), 256, SMEM_MED3>>>(
        p_opt, p_wog, nullptr, p_ot, HID, HID, b_out_gate, nullptr, p_op);

    // 7) clip = out @ w_proj^T + b
    mma_gemm<3, 64, 64, 2, 2, 8><<<dim3(CLIP_D / 64, BATCH / 64), 256, SMEM_SML3>>>(
        p_ot, p_wpj, out_clip, nullptr, HID, CLIP_D, b_proj, nullptr, nullptr);
}